// round 1
// baseline (speedup 1.0000x reference)
#include <cuda_runtime.h>
#include <math.h>

#define NN 50000
#define EE 640000
#define DD 128
#define EDIM 64
#define HH 4
#define HC 128
#define EN (EE+NN)

// ---------------- scratch (device globals; no allocation) ----------------
__device__ float g_xl[NN*HC];
__device__ float g_xr[NN*HC];
__device__ float g_loop[NN*EDIM];
__device__ float g_deg[NN];
__device__ float g_amax[NN*HH];
__device__ float g_denom[NN*HH];
__device__ float g_agg[NN*HC];
__device__ float g_e[(size_t)EN*HC];      // 353 MB e-projection
__device__ float g_h[NN*DD];
__device__ float g_mid[NN*2*DD];
__device__ float g_mlp[NN*DD];

template<int B> __device__ __forceinline__ float* bufsel(const float* ext){
    if constexpr (B==0) return const_cast<float*>(ext);
    else if constexpr (B==1) return g_xl;
    else if constexpr (B==2) return g_xr;
    else if constexpr (B==3) return g_loop;
    else if constexpr (B==4) return g_e;
    else if constexpr (B==6) return g_h;
    else if constexpr (B==7) return g_mid;
    else return g_mlp;
}

__device__ __forceinline__ void atomicMaxF(float* a, float v){
    if (v >= 0.f) atomicMax((int*)a, __float_as_int(v));
    else          atomicMin((unsigned int*)a, __float_as_uint(v));
}

// ---------------- init + ei_sl output ----------------
__global__ void k_init(float* __restrict__ out_ei, const int* __restrict__ ei){
    int i = blockIdx.x*blockDim.x + threadIdx.x;
    if (i < NN*HC)   g_agg[i] = 0.f;
    if (i < NN*EDIM) g_loop[i] = 0.f;
    if (i < NN)      g_deg[i] = 0.f;
    if (i < NN*HH){  g_amax[i] = -INFINITY; g_denom[i] = 0.f; }
    if (i < EN){
        int s = (i < EE) ? ei[i]     : (i-EE);
        int d = (i < EE) ? ei[EE+i]  : (i-EE);
        out_ei[i]      = (float)s;
        out_ei[EN+i]   = (float)d;
    }
}

// ---------------- self-loop attr: segment sum + degree ----------------
__global__ void k_loopsum(const int* __restrict__ ei, const float* __restrict__ ea){
    int i = blockIdx.x*blockDim.x + threadIdx.x;
    if (i >= EE*EDIM) return;
    int e = i >> 6, k = i & 63;
    int dst = ei[EE+e];
    atomicAdd(&g_loop[dst*EDIM + k], ea[i]);
    if (k == 0) atomicAdd(&g_deg[dst], 1.f);
}

__global__ void k_loopdiv(){
    int i = blockIdx.x*blockDim.x + threadIdx.x;
    if (i >= NN*EDIM) return;
    float d = g_deg[i >> 6];
    g_loop[i] = g_loop[i] / fmaxf(d, 1.f);
}

// ---------------- generic SGEMM: C = A * B^T (+bias)(+gelu) ----------------
// 64x64 tile, BK=16, 256 threads, 4x4 microtile
template<int ABUF, int CBUF, bool BIAS, bool GELU>
__global__ __launch_bounds__(256) void sgemm(
    const float* __restrict__ Aext, const float* __restrict__ Bw,
    const float* __restrict__ bias, float* __restrict__ Cext,
    int M, int Ncol, int K, size_t coff)
{
    const float* A = bufsel<ABUF>(Aext);
    float* C = bufsel<CBUF>((const float*)Cext);
    __shared__ float As[64][17];
    __shared__ float Bs[64][17];
    int tid = threadIdx.x;
    int tx = tid & 15, ty = tid >> 4;
    int row0 = blockIdx.y * 64, col0 = blockIdx.x * 64;
    float acc[4][4] = {};
    for (int k0 = 0; k0 < K; k0 += 16){
        #pragma unroll
        for (int i = 0; i < 4; i++){
            int idx = tid + i*256;
            int m = idx >> 4, kk = idx & 15;
            int gm = row0 + m;
            As[m][kk] = (gm < M) ? A[(size_t)gm*K + k0 + kk] : 0.f;
            Bs[m][kk] = Bw[(size_t)(col0+m)*K + k0 + kk];
        }
        __syncthreads();
        #pragma unroll
        for (int k = 0; k < 16; k++){
            float a[4], b[4];
            #pragma unroll
            for (int i=0;i<4;i++) a[i] = As[ty*4+i][k];
            #pragma unroll
            for (int j=0;j<4;j++) b[j] = Bs[tx*4+j][k];
            #pragma unroll
            for (int i=0;i<4;i++)
                #pragma unroll
                for (int j=0;j<4;j++) acc[i][j] += a[i]*b[j];
        }
        __syncthreads();
    }
    #pragma unroll
    for (int i=0;i<4;i++){
        int gm = row0 + ty*4 + i;
        if (gm >= M) continue;
        #pragma unroll
        for (int j=0;j<4;j++){
            int gn = col0 + tx*4 + j;
            float v = acc[i][j];
            if (BIAS) v += bias[gn];
            if (GELU) v = 0.5f*v*(1.f + erff(v*0.70710678118654752f));
            C[coff + (size_t)gm*Ncol + gn] = v;
        }
    }
}

// ---------------- attention logits + segment max (warp per edge) ----------------
__global__ void k_logits(const int* __restrict__ ei, const float* __restrict__ att,
                         float* __restrict__ alpha){
    int t = blockIdx.x*blockDim.x + threadIdx.x;
    int r = t >> 5, lane = t & 31;
    if (r >= EN) return;
    int src = (r < EE) ? ei[r]    : (r-EE);
    int dst = (r < EE) ? ei[EE+r] : (r-EE);
    const float* xlp = g_xl + src*HC;
    const float* xrp = g_xr + dst*HC;
    const float* ep  = g_e + (size_t)r*HC;
    float p0,p1,p2,p3;
    {
        float gg;
        gg = xlp[lane]    + xrp[lane]    + ep[lane];    gg = (gg>0.f)?gg:0.2f*gg; p0 = gg*att[lane];
        gg = xlp[32+lane] + xrp[32+lane] + ep[32+lane]; gg = (gg>0.f)?gg:0.2f*gg; p1 = gg*att[32+lane];
        gg = xlp[64+lane] + xrp[64+lane] + ep[64+lane]; gg = (gg>0.f)?gg:0.2f*gg; p2 = gg*att[64+lane];
        gg = xlp[96+lane] + xrp[96+lane] + ep[96+lane]; gg = (gg>0.f)?gg:0.2f*gg; p3 = gg*att[96+lane];
    }
    #pragma unroll
    for (int o=16;o;o>>=1){
        p0 += __shfl_xor_sync(0xffffffffu, p0, o);
        p1 += __shfl_xor_sync(0xffffffffu, p1, o);
        p2 += __shfl_xor_sync(0xffffffffu, p2, o);
        p3 += __shfl_xor_sync(0xffffffffu, p3, o);
    }
    if (lane == 0){
        alpha[r*4+0]=p0; alpha[r*4+1]=p1; alpha[r*4+2]=p2; alpha[r*4+3]=p3;
        atomicMaxF(&g_amax[dst*4+0], p0);
        atomicMaxF(&g_amax[dst*4+1], p1);
        atomicMaxF(&g_amax[dst*4+2], p2);
        atomicMaxF(&g_amax[dst*4+3], p3);
    }
}

// ---------------- exp + segment sum ----------------
__global__ void k_expdenom(const int* __restrict__ ei, float* __restrict__ alpha){
    int i = blockIdx.x*blockDim.x + threadIdx.x;
    if (i >= EN*HH) return;
    int r = i >> 2, h = i & 3;
    int dst = (r < EE) ? ei[EE+r] : (r-EE);
    float ex = expf(alpha[i] - g_amax[dst*4+h]);
    alpha[i] = ex;
    atomicAdd(&g_denom[dst*4+h], ex);
}

// ---------------- normalize alpha + scatter-aggregate (warp per edge) ----------------
__global__ void k_agg(const int* __restrict__ ei, float* __restrict__ alpha){
    int t = blockIdx.x*blockDim.x + threadIdx.x;
    int r = t >> 5, lane = t & 31;
    if (r >= EN) return;
    int src = (r < EE) ? ei[r]    : (r-EE);
    int dst = (r < EE) ? ei[EE+r] : (r-EE);
    float a0 = alpha[r*4+0] / g_denom[dst*4+0];
    float a1 = alpha[r*4+1] / g_denom[dst*4+1];
    float a2 = alpha[r*4+2] / g_denom[dst*4+2];
    float a3 = alpha[r*4+3] / g_denom[dst*4+3];
    __syncwarp();
    if (lane == 0){
        alpha[r*4+0]=a0; alpha[r*4+1]=a1; alpha[r*4+2]=a2; alpha[r*4+3]=a3;
    }
    const float* xlp = g_xl + src*HC;
    float* ag = g_agg + dst*HC;
    atomicAdd(&ag[lane],    a0 * xlp[lane]);
    atomicAdd(&ag[32+lane], a1 * xlp[32+lane]);
    atomicAdd(&ag[64+lane], a2 * xlp[64+lane]);
    atomicAdd(&ag[96+lane], a3 * xlp[96+lane]);
}

// ---------------- residual + LayerNorm (warp per node) ----------------
// MODE 0: g_h  = LN(x + g_agg + gat_bias)     MODE 1: out = LN(g_h + g_mlp)
template<int MODE>
__global__ void k_ln(const float* __restrict__ aext, const float* __restrict__ bias,
                     const float* __restrict__ gam, const float* __restrict__ bet,
                     float* __restrict__ oext){
    int t = blockIdx.x*blockDim.x + threadIdx.x;
    int n = t >> 5, lane = t & 31;
    if (n >= NN) return;
    const float* A = (MODE==0) ? aext : g_h;
    const float* B = (MODE==0) ? g_agg : g_mlp;
    float* O       = (MODE==0) ? g_h : oext;
    float v[4];
    #pragma unroll
    for (int j=0;j<4;j++){
        int d = j*32 + lane;
        float x = A[n*128+d] + B[n*128+d];
        if (MODE==0) x += bias[d];
        v[j] = x;
    }
    float s = v[0]+v[1]+v[2]+v[3];
    #pragma unroll
    for (int o=16;o;o>>=1) s += __shfl_xor_sync(0xffffffffu, s, o);
    float mu = s * (1.f/128.f);
    float q = 0.f;
    #pragma unroll
    for (int j=0;j<4;j++){ float dd = v[j]-mu; q += dd*dd; }
    #pragma unroll
    for (int o=16;o;o>>=1) q += __shfl_xor_sync(0xffffffffu, q, o);
    float rstd = rsqrtf(q*(1.f/128.f) + 1e-5f);
    #pragma unroll
    for (int j=0;j<4;j++){
        int d = j*32 + lane;
        O[n*128+d] = (v[j]-mu)*rstd*gam[d] + bet[d];
    }
}

// ---------------- launch ----------------
extern "C" void kernel_launch(void* const* d_in, const int* in_sizes, int n_in,
                              void* d_out, int out_size) {
    const float* x   = (const float*)d_in[0];
    const int*   ei  = (const int*)  d_in[1];
    const float* ea  = (const float*)d_in[2];
    const float* Wl  = (const float*)d_in[3];
    const float* bl  = (const float*)d_in[4];
    const float* Wr  = (const float*)d_in[5];
    const float* br  = (const float*)d_in[6];
    const float* We  = (const float*)d_in[7];
    const float* att = (const float*)d_in[8];
    const float* gb  = (const float*)d_in[9];
    const float* g1  = (const float*)d_in[10];
    const float* b1  = (const float*)d_in[11];
    const float* g2  = (const float*)d_in[12];
    const float* b2  = (const float*)d_in[13];
    const float* W1  = (const float*)d_in[14];
    const float* W2  = (const float*)d_in[15];

    float* out    = (float*)d_out;
    float* out_ei = out + (size_t)NN*DD;              // 2*(E+N)
    float* alpha  = out + (size_t)NN*DD + 2*(size_t)EN; // (E+N)*H

    const int T = 256;
    k_init<<<(NN*HC + T-1)/T, T>>>(out_ei, ei);
    k_loopsum<<<(EE*EDIM + T-1)/T, T>>>(ei, ea);
    k_loopdiv<<<(NN*EDIM + T-1)/T, T>>>();

    dim3 gN(2, (NN+63)/64);
    sgemm<0,1,true,false><<<gN, 256>>>(x, Wl, bl, nullptr, NN, 128, 128, 0);
    sgemm<0,2,true,false><<<gN, 256>>>(x, Wr, br, nullptr, NN, 128, 128, 0);
    sgemm<0,4,false,false><<<dim3(2, EE/64), 256>>>(ea, We, nullptr, nullptr, EE, 128, 64, 0);
    sgemm<3,4,false,false><<<dim3(2, (NN+63)/64), 256>>>(nullptr, We, nullptr, nullptr, NN, 128, 64, (size_t)EE*128);

    k_logits<<<((size_t)EN*32 + T-1)/T, T>>>(ei, att, alpha);
    k_expdenom<<<(EN*HH + T-1)/T, T>>>(ei, alpha);
    k_agg<<<((size_t)EN*32 + T-1)/T, T>>>(ei, alpha);

    k_ln<0><<<(NN*32 + T-1)/T, T>>>(x, gb, g1, b1, nullptr);
    sgemm<6,7,false,true><<<dim3(4, (NN+63)/64), 256>>>(nullptr, W1, nullptr, nullptr, NN, 256, 128, 0);
    sgemm<7,8,false,false><<<dim3(2, (NN+63)/64), 256>>>(nullptr, W2, nullptr, nullptr, NN, 128, 256, 0);
    k_ln<1><<<(NN*32 + T-1)/T, T>>>(nullptr, nullptr, g2, b2, out);
}

// round 2
// speedup vs baseline: 1.2500x; 1.2500x over previous
#include <cuda_runtime.h>
#include <math.h>

#define NN 50000
#define EE 640000
#define DD 128
#define EDIM 64
#define HH 4
#define HC 128
#define EN (EE+NN)

// ---------------- scratch (device globals; no allocation) ----------------
__device__ float g_xl[NN*HC];
__device__ float g_xr[NN*HC];
__device__ float g_loop[NN*EDIM];
__device__ float g_h[NN*DD];
__device__ float g_mid[NN*2*DD];
__device__ float g_mlp[NN*DD];
__device__ int   g_cnt[NN];
__device__ int   g_cur[NN];
__device__ int   g_off[NN+1];
__device__ int   g_srow[EE];
__device__ int   g_ssrc[EE];

template<int B> __device__ __forceinline__ float* bufsel(const float* ext){
    if constexpr (B==0) return const_cast<float*>(ext);
    else if constexpr (B==1) return g_xl;
    else if constexpr (B==2) return g_xr;
    else if constexpr (B==6) return g_h;
    else if constexpr (B==7) return g_mid;
    else return g_mlp;
}

// ---------------- packed f32x2 helpers ----------------
__device__ __forceinline__ unsigned long long pack2(float lo, float hi){
    unsigned long long r; asm("mov.b64 %0, {%1,%2};" : "=l"(r) : "f"(lo), "f"(hi)); return r;
}
__device__ __forceinline__ void unpack2(unsigned long long v, float& lo, float& hi){
    asm("mov.b64 {%0,%1}, %2;" : "=f"(lo), "=f"(hi) : "l"(v));
}
__device__ __forceinline__ void ffma2(unsigned long long &d, unsigned long long a, unsigned long long b){
    asm("fma.rn.f32x2 %0, %1, %2, %0;" : "+l"(d) : "l"(a), "l"(b));
}

// ---------------- init: zero counters + ei_sl output ----------------
__global__ void k_init(float* __restrict__ out_ei, const int* __restrict__ ei){
    int i = blockIdx.x*blockDim.x + threadIdx.x;
    if (i < NN) g_cnt[i] = 0;
    if (i < EN){
        int s = (i < EE) ? ei[i]     : (i-EE);
        int d = (i < EE) ? ei[EE+i]  : (i-EE);
        out_ei[i]    = (float)s;
        out_ei[EN+i] = (float)d;
    }
}

// ---------------- CSR build ----------------
__global__ void k_count(const int* __restrict__ ei){
    int i = blockIdx.x*blockDim.x + threadIdx.x;
    if (i < EE) atomicAdd(&g_cnt[ei[EE+i]], 1);
}

__global__ void k_scan(){
    __shared__ int part[1024];
    int t = threadIdx.x;
    const int chunk = (NN + 1023)/1024;   // 49
    int b = t*chunk;
    int sum = 0;
    for (int i = 0; i < chunk; i++){ int idx = b+i; if (idx < NN) sum += g_cnt[idx]; }
    part[t] = sum;
    __syncthreads();
    for (int off = 1; off < 1024; off <<= 1){
        int v = (t >= off) ? part[t-off] : 0;
        __syncthreads();
        part[t] += v;
        __syncthreads();
    }
    int run = (t == 0) ? 0 : part[t-1];
    for (int i = 0; i < chunk; i++){
        int idx = b+i;
        if (idx < NN){ g_off[idx] = run; g_cur[idx] = run; run += g_cnt[idx]; }
    }
    if (t == 1023) g_off[NN] = run;
}

__global__ void k_scatter(const int* __restrict__ ei){
    int i = blockIdx.x*blockDim.x + threadIdx.x;
    if (i >= EE) return;
    int d = ei[EE+i];
    int p = atomicAdd(&g_cur[d], 1);
    g_srow[p] = i;
    g_ssrc[p] = ei[i];
}

// ---------------- loop attr: CSR gather mean (warp per node) ----------------
__global__ void k_loopattr(const float* __restrict__ ea){
    int t = blockIdx.x*blockDim.x + threadIdx.x;
    int n = t >> 5, lane = t & 31;
    if (n >= NN) return;
    int beg = g_off[n], end = g_off[n+1];
    float a0 = 0.f, a1 = 0.f;
    for (int idx = beg; idx < end; idx++){
        int row = g_srow[idx];
        a0 += ea[(size_t)row*EDIM + lane];
        a1 += ea[(size_t)row*EDIM + 32 + lane];
    }
    float inv = 1.f / fmaxf((float)(end-beg), 1.f);
    g_loop[(size_t)n*EDIM + lane]      = a0*inv;
    g_loop[(size_t)n*EDIM + 32 + lane] = a1*inv;
}

// ---------------- generic SGEMM: C = A * B^T (+bias)(+gelu), f32x2 inner ----------------
// 64x64 tile, BK=16, 256 threads, 4x4 microtile (2x FFMA2 pairs per row)
template<int ABUF, int CBUF, bool BIAS, bool GELU>
__global__ __launch_bounds__(256) void sgemm(
    const float* __restrict__ Aext, const float* __restrict__ Bw,
    const float* __restrict__ bias, float* __restrict__ Cext,
    int M, int Ncol, int K)
{
    const float* A = bufsel<ABUF>(Aext);
    float* C = bufsel<CBUF>((const float*)Cext);
    __shared__ float As[64][17];
    __shared__ float Bst[16][66];   // [k][col], padded even for float2
    int tid = threadIdx.x;
    int tx = tid & 15, ty = tid >> 4;
    int row0 = blockIdx.y * 64, col0 = blockIdx.x * 64;
    unsigned long long acc[4][2];
    #pragma unroll
    for (int i=0;i<4;i++){ acc[i][0]=0ULL; acc[i][1]=0ULL; }
    for (int k0 = 0; k0 < K; k0 += 16){
        #pragma unroll
        for (int i = 0; i < 4; i++){
            int idx = tid + i*256;
            int m = idx >> 4, kk = idx & 15;
            int gm = row0 + m;
            As[m][kk] = (gm < M) ? A[(size_t)gm*K + k0 + kk] : 0.f;
            Bst[kk][m] = Bw[(size_t)(col0+m)*K + k0 + kk];
        }
        __syncthreads();
        #pragma unroll
        for (int k = 0; k < 16; k++){
            unsigned long long b0 = *(const unsigned long long*)&Bst[k][tx*4];
            unsigned long long b1 = *(const unsigned long long*)&Bst[k][tx*4+2];
            #pragma unroll
            for (int i=0;i<4;i++){
                float a = As[ty*4+i][k];
                unsigned long long a2 = pack2(a, a);
                ffma2(acc[i][0], a2, b0);
                ffma2(acc[i][1], a2, b1);
            }
        }
        __syncthreads();
    }
    #pragma unroll
    for (int i=0;i<4;i++){
        int gm = row0 + ty*4 + i;
        if (gm >= M) continue;
        float v[4];
        unpack2(acc[i][0], v[0], v[1]);
        unpack2(acc[i][1], v[2], v[3]);
        #pragma unroll
        for (int j=0;j<4;j++){
            int gn = col0 + tx*4 + j;
            float val = v[j];
            if (BIAS) val += bias[gn];
            if (GELU) val = 0.5f*val*(1.f + erff(val*0.70710678118654752f));
            C[(size_t)gm*Ncol + gn] = val;
        }
    }
}

// ---------------- fused e-projection + attention logits ----------------
// block: 64 edge-rows x 128 comps, K=64. 128 threads, micro 8 edges x 8 comps (4 f32x2 pairs).
// comp mapping: thread tx owns pairs (tx*2+32j, tx*2+1+32j) for head j in 0..3.
__global__ __launch_bounds__(128) void k_elogits(
    const int* __restrict__ ei, const float* __restrict__ ea,
    const float* __restrict__ We, const float* __restrict__ att,
    float* __restrict__ alpha)
{
    __shared__ float As[16][66];    // [k][edge]
    __shared__ float Bs[16][130];   // [k][comp]
    __shared__ int s_src[64], s_dst[64];
    int tid = threadIdx.x;
    int tx = tid & 15, ty = tid >> 4;     // ty 0..7
    int row0 = blockIdx.x * 64;

    if (tid < 64){
        int e = row0 + tid;
        int s, d;
        if (e < EE){ s = ei[e]; d = ei[EE+e]; }
        else if (e < EN){ s = e-EE; d = e-EE; }
        else { s = 0; d = 0; }
        s_src[tid] = s; s_dst[tid] = d;
    }

    unsigned long long acc[8][4];
    #pragma unroll
    for (int i=0;i<8;i++)
        #pragma unroll
        for (int j=0;j<4;j++) acc[i][j] = 0ULL;

    for (int k0 = 0; k0 < EDIM; k0 += 16){
        #pragma unroll
        for (int l = 0; l < 8; l++){
            int idx = tid + l*128;
            int e = idx >> 4, kk = idx & 15;
            int eg = row0 + e;
            float v;
            if (eg < EE)      v = ea[(size_t)eg*EDIM + k0 + kk];
            else if (eg < EN) v = g_loop[(size_t)(eg-EE)*EDIM + k0 + kk];
            else              v = 0.f;
            As[kk][e] = v;
        }
        #pragma unroll
        for (int l = 0; l < 16; l++){
            int idx = tid + l*128;
            int c = idx >> 4, kk = idx & 15;
            Bs[kk][c] = We[(size_t)c*EDIM + k0 + kk];
        }
        __syncthreads();
        #pragma unroll
        for (int k = 0; k < 16; k++){
            unsigned long long b2[4];
            #pragma unroll
            for (int j=0;j<4;j++)
                b2[j] = *(const unsigned long long*)&Bs[k][tx*2 + 32*j];
            #pragma unroll
            for (int i=0;i<8;i++){
                float a = As[k][ty*8+i];
                unsigned long long a2 = pack2(a, a);
                #pragma unroll
                for (int j=0;j<4;j++) ffma2(acc[i][j], a2, b2[j]);
            }
        }
        __syncthreads();
    }

    float attv[8];
    #pragma unroll
    for (int j=0;j<4;j++){
        attv[2*j]   = att[tx*2 + 32*j];
        attv[2*j+1] = att[tx*2+1 + 32*j];
    }

    float4* a4 = (float4*)alpha;
    #pragma unroll
    for (int i=0;i<8;i++){
        int el = ty*8 + i;
        int eg = row0 + el;
        int src = s_src[el], dst = s_dst[el];
        const float* xlp = g_xl + (size_t)src*HC;
        const float* xrp = g_xr + (size_t)dst*HC;
        float p[4];
        #pragma unroll
        for (int j=0;j<4;j++){
            int c0 = tx*2 + 32*j;
            float v0, v1; unpack2(acc[i][j], v0, v1);
            v0 += xlp[c0]   + xrp[c0];
            v1 += xlp[c0+1] + xrp[c0+1];
            v0 = (v0 > 0.f) ? v0 : 0.2f*v0;
            v1 = (v1 > 0.f) ? v1 : 0.2f*v1;
            p[j] = v0*attv[2*j] + v1*attv[2*j+1];
        }
        #pragma unroll
        for (int off = 1; off < 16; off <<= 1){
            #pragma unroll
            for (int j=0;j<4;j++) p[j] += __shfl_xor_sync(0xffffffffu, p[j], off);
        }
        if (tx == 0 && eg < EN)
            a4[eg] = make_float4(p[0], p[1], p[2], p[3]);
    }
}

// ---------------- segment softmax + aggregate + residual + LN1 (warp per node) ----------------
__global__ void k_smagg(const float* __restrict__ x, const float* __restrict__ gbias,
                        const float* __restrict__ g1, const float* __restrict__ b1,
                        float* __restrict__ alpha)
{
    int t = blockIdx.x*blockDim.x + threadIdx.x;
    int n = t >> 5, lane = t & 31;
    if (n >= NN) return;
    int beg = g_off[n], end = g_off[n+1];
    float4* a4 = (float4*)alpha;

    float4 lsl = a4[EE+n];   // self-loop raw logits
    float m0 = lsl.x, m1 = lsl.y, m2 = lsl.z, m3 = lsl.w;
    for (int idx = beg + lane; idx < end; idx += 32){
        float4 l = a4[g_srow[idx]];
        m0 = fmaxf(m0, l.x); m1 = fmaxf(m1, l.y);
        m2 = fmaxf(m2, l.z); m3 = fmaxf(m3, l.w);
    }
    #pragma unroll
    for (int o = 16; o; o >>= 1){
        m0 = fmaxf(m0, __shfl_xor_sync(0xffffffffu, m0, o));
        m1 = fmaxf(m1, __shfl_xor_sync(0xffffffffu, m1, o));
        m2 = fmaxf(m2, __shfl_xor_sync(0xffffffffu, m2, o));
        m3 = fmaxf(m3, __shfl_xor_sync(0xffffffffu, m3, o));
    }
    float s0 = (lane==0) ? expf(lsl.x - m0) : 0.f;
    float s1 = (lane==0) ? expf(lsl.y - m1) : 0.f;
    float s2 = (lane==0) ? expf(lsl.z - m2) : 0.f;
    float s3 = (lane==0) ? expf(lsl.w - m3) : 0.f;
    for (int idx = beg + lane; idx < end; idx += 32){
        float4 l = a4[g_srow[idx]];
        s0 += expf(l.x - m0); s1 += expf(l.y - m1);
        s2 += expf(l.z - m2); s3 += expf(l.w - m3);
    }
    #pragma unroll
    for (int o = 16; o; o >>= 1){
        s0 += __shfl_xor_sync(0xffffffffu, s0, o);
        s1 += __shfl_xor_sync(0xffffffffu, s1, o);
        s2 += __shfl_xor_sync(0xffffffffu, s2, o);
        s3 += __shfl_xor_sync(0xffffffffu, s3, o);
    }
    float i0 = 1.f/s0, i1 = 1.f/s1, i2 = 1.f/s2, i3 = 1.f/s3;

    float asl0 = expf(lsl.x - m0)*i0, asl1 = expf(lsl.y - m1)*i1;
    float asl2 = expf(lsl.z - m2)*i2, asl3 = expf(lsl.w - m3)*i3;
    if (lane == 0) a4[EE+n] = make_float4(asl0, asl1, asl2, asl3);
    for (int idx = beg + lane; idx < end; idx += 32){
        int row = g_srow[idx];
        float4 l = a4[row];
        a4[row] = make_float4(expf(l.x - m0)*i0, expf(l.y - m1)*i1,
                              expf(l.z - m2)*i2, expf(l.w - m3)*i3);
    }
    __syncwarp();

    float acc0 = 0.f, acc1 = 0.f, acc2 = 0.f, acc3 = 0.f;
    for (int idx = beg; idx < end; idx++){
        int row = g_srow[idx], src = g_ssrc[idx];
        float4 a = a4[row];
        const float* xlp = g_xl + (size_t)src*HC;
        acc0 += a.x * xlp[lane];
        acc1 += a.y * xlp[32+lane];
        acc2 += a.z * xlp[64+lane];
        acc3 += a.w * xlp[96+lane];
    }
    const float* xn = g_xl + (size_t)n*HC;
    acc0 += asl0 * xn[lane];
    acc1 += asl1 * xn[32+lane];
    acc2 += asl2 * xn[64+lane];
    acc3 += asl3 * xn[96+lane];

    // residual + LN1
    float v0 = acc0 + x[(size_t)n*DD + lane]      + gbias[lane];
    float v1 = acc1 + x[(size_t)n*DD + 32 + lane] + gbias[32+lane];
    float v2 = acc2 + x[(size_t)n*DD + 64 + lane] + gbias[64+lane];
    float v3 = acc3 + x[(size_t)n*DD + 96 + lane] + gbias[96+lane];
    float s = v0+v1+v2+v3;
    #pragma unroll
    for (int o = 16; o; o >>= 1) s += __shfl_xor_sync(0xffffffffu, s, o);
    float mu = s * (1.f/128.f);
    float q = (v0-mu)*(v0-mu) + (v1-mu)*(v1-mu) + (v2-mu)*(v2-mu) + (v3-mu)*(v3-mu);
    #pragma unroll
    for (int o = 16; o; o >>= 1) q += __shfl_xor_sync(0xffffffffu, q, o);
    float rstd = rsqrtf(q*(1.f/128.f) + 1e-5f);
    g_h[(size_t)n*DD + lane]      = (v0-mu)*rstd*g1[lane]      + b1[lane];
    g_h[(size_t)n*DD + 32 + lane] = (v1-mu)*rstd*g1[32+lane]   + b1[32+lane];
    g_h[(size_t)n*DD + 64 + lane] = (v2-mu)*rstd*g1[64+lane]   + b1[64+lane];
    g_h[(size_t)n*DD + 96 + lane] = (v3-mu)*rstd*g1[96+lane]   + b1[96+lane];
}

// ---------------- residual + LayerNorm 2 (warp per node) ----------------
__global__ void k_ln2(const float* __restrict__ gam, const float* __restrict__ bet,
                      float* __restrict__ O){
    int t = blockIdx.x*blockDim.x + threadIdx.x;
    int n = t >> 5, lane = t & 31;
    if (n >= NN) return;
    float v[4];
    #pragma unroll
    for (int j=0;j<4;j++){
        int d = j*32 + lane;
        v[j] = g_h[(size_t)n*DD + d] + g_mlp[(size_t)n*DD + d];
    }
    float s = v[0]+v[1]+v[2]+v[3];
    #pragma unroll
    for (int o=16;o;o>>=1) s += __shfl_xor_sync(0xffffffffu, s, o);
    float mu = s * (1.f/128.f);
    float q = 0.f;
    #pragma unroll
    for (int j=0;j<4;j++){ float dd = v[j]-mu; q += dd*dd; }
    #pragma unroll
    for (int o=16;o;o>>=1) q += __shfl_xor_sync(0xffffffffu, q, o);
    float rstd = rsqrtf(q*(1.f/128.f) + 1e-5f);
    #pragma unroll
    for (int j=0;j<4;j++){
        int d = j*32 + lane;
        O[(size_t)n*DD + d] = (v[j]-mu)*rstd*gam[d] + bet[d];
    }
}

// ---------------- launch ----------------
extern "C" void kernel_launch(void* const* d_in, const int* in_sizes, int n_in,
                              void* d_out, int out_size) {
    const float* x   = (const float*)d_in[0];
    const int*   ei  = (const int*)  d_in[1];
    const float* ea  = (const float*)d_in[2];
    const float* Wl  = (const float*)d_in[3];
    const float* bl  = (const float*)d_in[4];
    const float* Wr  = (const float*)d_in[5];
    const float* br  = (const float*)d_in[6];
    const float* We  = (const float*)d_in[7];
    const float* att = (const float*)d_in[8];
    const float* gb  = (const float*)d_in[9];
    const float* g1  = (const float*)d_in[10];
    const float* b1  = (const float*)d_in[11];
    const float* g2  = (const float*)d_in[12];
    const float* b2  = (const float*)d_in[13];
    const float* W1  = (const float*)d_in[14];
    const float* W2  = (const float*)d_in[15];

    float* out    = (float*)d_out;
    float* out_ei = out + (size_t)NN*DD;
    float* alpha  = out + (size_t)NN*DD + 2*(size_t)EN;

    const int T = 256;
    k_init<<<(EN + T-1)/T, T>>>(out_ei, ei);
    k_count<<<(EE + T-1)/T, T>>>(ei);
    k_scan<<<1, 1024>>>();
    k_scatter<<<(EE + T-1)/T, T>>>(ei);
    k_loopattr<<<(NN*32 + T-1)/T, T>>>(ea);

    dim3 gN(2, (NN+63)/64);
    sgemm<0,1,true,false><<<gN, 256>>>(x, Wl, bl, nullptr, NN, 128, 128);
    sgemm<0,2,true,false><<<gN, 256>>>(x, Wr, br, nullptr, NN, 128, 128);

    k_elogits<<<(EN + 63)/64, 128>>>(ei, ea, We, att, alpha);
    k_smagg<<<(NN*32 + T-1)/T, T>>>(x, gb, g1, b1, alpha);

    sgemm<6,7,false,true><<<dim3(4, (NN+63)/64), 256>>>(nullptr, W1, nullptr, nullptr, NN, 256, 128);
    sgemm<7,8,false,false><<<dim3(2, (NN+63)/64), 256>>>(nullptr, W2, nullptr, nullptr, NN, 128, 256);
    k_ln2<<<(NN*32 + T-1)/T, T>>>(g2, b2, out);
}

// round 3
// speedup vs baseline: 1.6653x; 1.3322x over previous
#include <cuda_runtime.h>
#include <math.h>

#define NN 50000
#define EE 640000
#define DD 128
#define EDIM 64
#define HH 4
#define HC 128
#define EN (EE+NN)

// ---------------- scratch (device globals; no allocation) ----------------
__device__ float g_xl[NN*HC];
__device__ float g_xr[NN*HC];
__device__ float g_loop[NN*EDIM];
__device__ float g_h[NN*DD];
__device__ float g_mid[NN*2*DD];
__device__ float g_mlp[NN*DD];
__device__ int   g_cnt[NN];
__device__ int   g_cur[NN];
__device__ int   g_off[NN+1];
__device__ int   g_srow[EE];
__device__ int   g_ssrc[EE];

template<int B> __device__ __forceinline__ float* bufsel(const float* ext){
    if constexpr (B==0) return const_cast<float*>(ext);
    else if constexpr (B==1) return g_xl;
    else if constexpr (B==2) return g_xr;
    else if constexpr (B==6) return g_h;
    else if constexpr (B==7) return g_mid;
    else return g_mlp;
}

// ---------------- packed f32x2 helpers ----------------
__device__ __forceinline__ unsigned long long pack2(float lo, float hi){
    unsigned long long r; asm("mov.b64 %0, {%1,%2};" : "=l"(r) : "f"(lo), "f"(hi)); return r;
}
__device__ __forceinline__ void unpack2(unsigned long long v, float& lo, float& hi){
    asm("mov.b64 {%0,%1}, %2;" : "=f"(lo), "=f"(hi) : "l"(v));
}
__device__ __forceinline__ void ffma2(unsigned long long &d, unsigned long long a, unsigned long long b){
    asm("fma.rn.f32x2 %0, %1, %2, %0;" : "+l"(d) : "l"(a), "l"(b));
}

// ---------------- init: zero counters + ei_sl output ----------------
__global__ void k_init(float* __restrict__ out_ei, const int* __restrict__ ei){
    int i = blockIdx.x*blockDim.x + threadIdx.x;
    if (i < NN) g_cnt[i] = 0;
    if (i < EN){
        int s = (i < EE) ? ei[i]     : (i-EE);
        int d = (i < EE) ? ei[EE+i]  : (i-EE);
        out_ei[i]    = (float)s;
        out_ei[EN+i] = (float)d;
    }
}

// ---------------- CSR build ----------------
__global__ void k_count(const int* __restrict__ ei){
    int i = blockIdx.x*blockDim.x + threadIdx.x;
    if (i < EE) atomicAdd(&g_cnt[ei[EE+i]], 1);
}

__global__ void k_scan(){
    __shared__ int part[1024];
    int t = threadIdx.x;
    const int chunk = (NN + 1023)/1024;
    int b = t*chunk;
    int sum = 0;
    for (int i = 0; i < chunk; i++){ int idx = b+i; if (idx < NN) sum += g_cnt[idx]; }
    part[t] = sum;
    __syncthreads();
    for (int off = 1; off < 1024; off <<= 1){
        int v = (t >= off) ? part[t-off] : 0;
        __syncthreads();
        part[t] += v;
        __syncthreads();
    }
    int run = (t == 0) ? 0 : part[t-1];
    for (int i = 0; i < chunk; i++){
        int idx = b+i;
        if (idx < NN){ g_off[idx] = run; g_cur[idx] = run; run += g_cnt[idx]; }
    }
    if (t == 1023) g_off[NN] = run;
}

__global__ void k_scatter(const int* __restrict__ ei){
    int i = blockIdx.x*blockDim.x + threadIdx.x;
    if (i >= EE) return;
    int d = ei[EE+i];
    int p = atomicAdd(&g_cur[d], 1);
    g_srow[p] = i;
    g_ssrc[p] = ei[i];
}

// ---------------- loop attr: CSR gather mean (warp per node, float2) ----------------
__global__ void k_loopattr(const float* __restrict__ ea){
    int t = blockIdx.x*blockDim.x + threadIdx.x;
    int n = t >> 5, lane = t & 31;
    if (n >= NN) return;
    int beg = g_off[n], end = g_off[n+1];
    float a0 = 0.f, a1 = 0.f;
    for (int idx = beg; idx < end; idx++){
        int row = g_srow[idx];
        float2 v = *(const float2*)&ea[(size_t)row*EDIM + lane*2];
        a0 += v.x; a1 += v.y;
    }
    float inv = 1.f / fmaxf((float)(end-beg), 1.f);
    *(float2*)&g_loop[(size_t)n*EDIM + lane*2] = make_float2(a0*inv, a1*inv);
}

// ---------------- SGEMM: C = A * B^T (+bias)(+gelu) ----------------
// 128x128 tile, BK=16, 256 threads, 8x8 microtile, f32x2 inner loop
template<int ABUF, int CBUF, bool BIAS, bool GELU>
__global__ __launch_bounds__(256, 2) void sgemm(
    const float* __restrict__ Aext, const float* __restrict__ Bw,
    const float* __restrict__ bias, float* __restrict__ Cext,
    int M, int Ncol, int K)
{
    const float* A = bufsel<ABUF>(Aext);
    float* C = bufsel<CBUF>((const float*)Cext);
    __shared__ float As[16][132];   // [k][m]
    __shared__ float Bs[16][132];   // [k][n]
    int tid = threadIdx.x;
    int tx = tid & 15, ty = tid >> 4;
    int row0 = blockIdx.y * 128, col0 = blockIdx.x * 128;
    unsigned long long acc[8][4];
    #pragma unroll
    for (int i=0;i<8;i++)
        #pragma unroll
        for (int j=0;j<4;j++) acc[i][j] = 0ULL;

    for (int k0 = 0; k0 < K; k0 += 16){
        #pragma unroll
        for (int i = 0; i < 2; i++){
            int linear = tid + i*256;       // 0..511
            int m = linear >> 2, c4 = (linear & 3)*4;
            int gm = row0 + m;
            float4 av = (gm < M) ? *(const float4*)&A[(size_t)gm*K + k0 + c4]
                                 : make_float4(0.f,0.f,0.f,0.f);
            As[c4+0][m] = av.x; As[c4+1][m] = av.y; As[c4+2][m] = av.z; As[c4+3][m] = av.w;
            float4 bv = *(const float4*)&Bw[(size_t)(col0+m)*K + k0 + c4];
            Bs[c4+0][m] = bv.x; Bs[c4+1][m] = bv.y; Bs[c4+2][m] = bv.z; Bs[c4+3][m] = bv.w;
        }
        __syncthreads();
        #pragma unroll
        for (int k = 0; k < 16; k++){
            float4 b0 = *(const float4*)&Bs[k][tx*8];
            float4 b1 = *(const float4*)&Bs[k][tx*8+4];
            unsigned long long bb[4];
            bb[0] = pack2(b0.x,b0.y); bb[1] = pack2(b0.z,b0.w);
            bb[2] = pack2(b1.x,b1.y); bb[3] = pack2(b1.z,b1.w);
            float4 a0 = *(const float4*)&As[k][ty*8];
            float4 a1 = *(const float4*)&As[k][ty*8+4];
            float ar[8] = {a0.x,a0.y,a0.z,a0.w,a1.x,a1.y,a1.z,a1.w};
            #pragma unroll
            for (int i=0;i<8;i++){
                unsigned long long a2 = pack2(ar[i], ar[i]);
                #pragma unroll
                for (int j=0;j<4;j++) ffma2(acc[i][j], a2, bb[j]);
            }
        }
        __syncthreads();
    }
    #pragma unroll
    for (int i=0;i<8;i++){
        int gm = row0 + ty*8 + i;
        if (gm >= M) continue;
        float v[8];
        #pragma unroll
        for (int j=0;j<4;j++) unpack2(acc[i][j], v[2*j], v[2*j+1]);
        int gn0 = col0 + tx*8;
        if (BIAS){
            float4 bsv0 = *(const float4*)&bias[gn0];
            float4 bsv1 = *(const float4*)&bias[gn0+4];
            v[0]+=bsv0.x; v[1]+=bsv0.y; v[2]+=bsv0.z; v[3]+=bsv0.w;
            v[4]+=bsv1.x; v[5]+=bsv1.y; v[6]+=bsv1.z; v[7]+=bsv1.w;
        }
        if (GELU){
            #pragma unroll
            for (int j=0;j<8;j++) v[j] = 0.5f*v[j]*(1.f + erff(v[j]*0.70710678118654752f));
        }
        *(float4*)&C[(size_t)gm*Ncol + gn0]     = make_float4(v[0],v[1],v[2],v[3]);
        *(float4*)&C[(size_t)gm*Ncol + gn0 + 4] = make_float4(v[4],v[5],v[6],v[7]);
    }
}

// ---------------- fused e-projection + attention logits ----------------
// 128 edges x 128 comps tile, K=64, 256 threads, 8x8 micro, f32x2.
// thread tx owns comps tx*8..tx*8+7 (all in head tx/4); ty owns edges ty*8..ty*8+7.
__global__ __launch_bounds__(256, 2) void k_elogits(
    const int* __restrict__ ei, const float* __restrict__ ea,
    const float* __restrict__ We, const float* __restrict__ att,
    float* __restrict__ alpha)
{
    __shared__ float As[16][132];   // [k][edge]
    __shared__ float Bs[16][132];   // [k][comp]
    __shared__ int s_src[128], s_dst[128];
    int tid = threadIdx.x;
    int tx = tid & 15, ty = tid >> 4;
    int row0 = blockIdx.x * 128;

    if (tid < 128){
        int e = row0 + tid;
        int s, d;
        if (e < EE){ s = ei[e]; d = ei[EE+e]; }
        else if (e < EN){ s = e-EE; d = e-EE; }
        else { s = 0; d = 0; }
        s_src[tid] = s; s_dst[tid] = d;
    }

    unsigned long long acc[8][4];
    #pragma unroll
    for (int i=0;i<8;i++)
        #pragma unroll
        for (int j=0;j<4;j++) acc[i][j] = 0ULL;

    for (int k0 = 0; k0 < EDIM; k0 += 16){
        #pragma unroll
        for (int i = 0; i < 2; i++){
            int linear = tid + i*256;
            int m = linear >> 2, c4 = (linear & 3)*4;
            int eg = row0 + m;
            float4 av;
            if (eg < EE)      av = *(const float4*)&ea[(size_t)eg*EDIM + k0 + c4];
            else if (eg < EN) av = *(const float4*)&g_loop[(size_t)(eg-EE)*EDIM + k0 + c4];
            else              av = make_float4(0.f,0.f,0.f,0.f);
            As[c4+0][m] = av.x; As[c4+1][m] = av.y; As[c4+2][m] = av.z; As[c4+3][m] = av.w;
            float4 bv = *(const float4*)&We[(size_t)m*EDIM + k0 + c4];
            Bs[c4+0][m] = bv.x; Bs[c4+1][m] = bv.y; Bs[c4+2][m] = bv.z; Bs[c4+3][m] = bv.w;
        }
        __syncthreads();
        #pragma unroll
        for (int k = 0; k < 16; k++){
            float4 b0 = *(const float4*)&Bs[k][tx*8];
            float4 b1 = *(const float4*)&Bs[k][tx*8+4];
            unsigned long long bb[4];
            bb[0] = pack2(b0.x,b0.y); bb[1] = pack2(b0.z,b0.w);
            bb[2] = pack2(b1.x,b1.y); bb[3] = pack2(b1.z,b1.w);
            float4 a0 = *(const float4*)&As[k][ty*8];
            float4 a1 = *(const float4*)&As[k][ty*8+4];
            float ar[8] = {a0.x,a0.y,a0.z,a0.w,a1.x,a1.y,a1.z,a1.w};
            #pragma unroll
            for (int i=0;i<8;i++){
                unsigned long long a2 = pack2(ar[i], ar[i]);
                #pragma unroll
                for (int j=0;j<4;j++) ffma2(acc[i][j], a2, bb[j]);
            }
        }
        __syncthreads();
    }

    int c0 = tx*8;
    float4 at0 = *(const float4*)&att[c0];
    float4 at1 = *(const float4*)&att[c0+4];
    float attv[8] = {at0.x,at0.y,at0.z,at0.w,at1.x,at1.y,at1.z,at1.w};
    int h = tx >> 2;
    bool writer = (tx & 3) == 0;

    #pragma unroll
    for (int i=0;i<8;i++){
        int el = ty*8 + i;
        int eg = row0 + el;
        int src = s_src[el], dst = s_dst[el];
        float4 xl0 = *(const float4*)&g_xl[(size_t)src*HC + c0];
        float4 xl1 = *(const float4*)&g_xl[(size_t)src*HC + c0 + 4];
        float4 xr0 = *(const float4*)&g_xr[(size_t)dst*HC + c0];
        float4 xr1 = *(const float4*)&g_xr[(size_t)dst*HC + c0 + 4];
        float xlr[8] = {xl0.x+xr0.x, xl0.y+xr0.y, xl0.z+xr0.z, xl0.w+xr0.w,
                        xl1.x+xr1.x, xl1.y+xr1.y, xl1.z+xr1.z, xl1.w+xr1.w};
        float v[8];
        #pragma unroll
        for (int j=0;j<4;j++) unpack2(acc[i][j], v[2*j], v[2*j+1]);
        float p = 0.f;
        #pragma unroll
        for (int j=0;j<8;j++){
            float gg = v[j] + xlr[j];
            gg = (gg > 0.f) ? gg : 0.2f*gg;
            p += gg * attv[j];
        }
        p += __shfl_xor_sync(0xffffffffu, p, 1);
        p += __shfl_xor_sync(0xffffffffu, p, 2);
        if (writer && eg < EN) alpha[(size_t)eg*4 + h] = p;
    }
}

// ---------------- segment softmax + aggregate + residual + LN1 (warp per node) ----------------
__global__ void k_smagg(const float* __restrict__ x, const float* __restrict__ gbias,
                        const float* __restrict__ g1, const float* __restrict__ b1,
                        float* __restrict__ alpha)
{
    int t = blockIdx.x*blockDim.x + threadIdx.x;
    int n = t >> 5, lane = t & 31;
    if (n >= NN) return;
    int beg = g_off[n], end = g_off[n+1];
    float4* a4 = (float4*)alpha;

    float4 lsl = a4[EE+n];   // self-loop raw logits
    float m0 = lsl.x, m1 = lsl.y, m2 = lsl.z, m3 = lsl.w;
    for (int idx = beg + lane; idx < end; idx += 32){
        float4 l = a4[g_srow[idx]];
        m0 = fmaxf(m0, l.x); m1 = fmaxf(m1, l.y);
        m2 = fmaxf(m2, l.z); m3 = fmaxf(m3, l.w);
    }
    #pragma unroll
    for (int o = 16; o; o >>= 1){
        m0 = fmaxf(m0, __shfl_xor_sync(0xffffffffu, m0, o));
        m1 = fmaxf(m1, __shfl_xor_sync(0xffffffffu, m1, o));
        m2 = fmaxf(m2, __shfl_xor_sync(0xffffffffu, m2, o));
        m3 = fmaxf(m3, __shfl_xor_sync(0xffffffffu, m3, o));
    }
    float s0 = (lane==0) ? expf(lsl.x - m0) : 0.f;
    float s1 = (lane==0) ? expf(lsl.y - m1) : 0.f;
    float s2 = (lane==0) ? expf(lsl.z - m2) : 0.f;
    float s3 = (lane==0) ? expf(lsl.w - m3) : 0.f;
    for (int idx = beg + lane; idx < end; idx += 32){
        float4 l = a4[g_srow[idx]];
        s0 += expf(l.x - m0); s1 += expf(l.y - m1);
        s2 += expf(l.z - m2); s3 += expf(l.w - m3);
    }
    #pragma unroll
    for (int o = 16; o; o >>= 1){
        s0 += __shfl_xor_sync(0xffffffffu, s0, o);
        s1 += __shfl_xor_sync(0xffffffffu, s1, o);
        s2 += __shfl_xor_sync(0xffffffffu, s2, o);
        s3 += __shfl_xor_sync(0xffffffffu, s3, o);
    }
    float i0 = 1.f/s0, i1 = 1.f/s1, i2 = 1.f/s2, i3 = 1.f/s3;

    float asl0 = expf(lsl.x - m0)*i0, asl1 = expf(lsl.y - m1)*i1;
    float asl2 = expf(lsl.z - m2)*i2, asl3 = expf(lsl.w - m3)*i3;
    if (lane == 0) a4[EE+n] = make_float4(asl0, asl1, asl2, asl3);
    for (int idx = beg + lane; idx < end; idx += 32){
        int row = g_srow[idx];
        float4 l = a4[row];
        a4[row] = make_float4(expf(l.x - m0)*i0, expf(l.y - m1)*i1,
                              expf(l.z - m2)*i2, expf(l.w - m3)*i3);
    }
    __syncwarp();

    // aggregate: lane owns comps lane*4..lane*4+3 (head = lane/8)
    int cbase = lane*4;
    int h = lane >> 3;
    float4 accv = make_float4(0.f,0.f,0.f,0.f);
    for (int idx = beg; idx < end; idx++){
        int row = g_srow[idx], src = g_ssrc[idx];
        float4 a = a4[row];
        float ah = (h==0) ? a.x : (h==1) ? a.y : (h==2) ? a.z : a.w;
        float4 xv = *(const float4*)&g_xl[(size_t)src*HC + cbase];
        accv.x += ah*xv.x; accv.y += ah*xv.y; accv.z += ah*xv.z; accv.w += ah*xv.w;
    }
    {
        float ah = (h==0) ? asl0 : (h==1) ? asl1 : (h==2) ? asl2 : asl3;
        float4 xv = *(const float4*)&g_xl[(size_t)n*HC + cbase];
        accv.x += ah*xv.x; accv.y += ah*xv.y; accv.z += ah*xv.z; accv.w += ah*xv.w;
    }

    // residual + bias + LN1
    float4 xres = *(const float4*)&x[(size_t)n*DD + cbase];
    float4 gb4  = *(const float4*)&gbias[cbase];
    float v0 = accv.x + xres.x + gb4.x;
    float v1 = accv.y + xres.y + gb4.y;
    float v2 = accv.z + xres.z + gb4.z;
    float v3 = accv.w + xres.w + gb4.w;
    float s = v0+v1+v2+v3;
    #pragma unroll
    for (int o = 16; o; o >>= 1) s += __shfl_xor_sync(0xffffffffu, s, o);
    float mu = s * (1.f/128.f);
    float q = (v0-mu)*(v0-mu) + (v1-mu)*(v1-mu) + (v2-mu)*(v2-mu) + (v3-mu)*(v3-mu);
    #pragma unroll
    for (int o = 16; o; o >>= 1) q += __shfl_xor_sync(0xffffffffu, q, o);
    float rstd = rsqrtf(q*(1.f/128.f) + 1e-5f);
    float4 g14 = *(const float4*)&g1[cbase];
    float4 b14 = *(const float4*)&b1[cbase];
    *(float4*)&g_h[(size_t)n*DD + cbase] = make_float4(
        (v0-mu)*rstd*g14.x + b14.x, (v1-mu)*rstd*g14.y + b14.y,
        (v2-mu)*rstd*g14.z + b14.z, (v3-mu)*rstd*g14.w + b14.w);
}

// ---------------- residual + LayerNorm 2 (warp per node, float4) ----------------
__global__ void k_ln2(const float* __restrict__ gam, const float* __restrict__ bet,
                      float* __restrict__ O){
    int t = blockIdx.x*blockDim.x + threadIdx.x;
    int n = t >> 5, lane = t & 31;
    if (n >= NN) return;
    int cbase = lane*4;
    float4 hv = *(const float4*)&g_h[(size_t)n*DD + cbase];
    float4 mv = *(const float4*)&g_mlp[(size_t)n*DD + cbase];
    float v0 = hv.x+mv.x, v1 = hv.y+mv.y, v2 = hv.z+mv.z, v3 = hv.w+mv.w;
    float s = v0+v1+v2+v3;
    #pragma unroll
    for (int o=16;o;o>>=1) s += __shfl_xor_sync(0xffffffffu, s, o);
    float mu = s * (1.f/128.f);
    float q = (v0-mu)*(v0-mu) + (v1-mu)*(v1-mu) + (v2-mu)*(v2-mu) + (v3-mu)*(v3-mu);
    #pragma unroll
    for (int o=16;o;o>>=1) q += __shfl_xor_sync(0xffffffffu, q, o);
    float rstd = rsqrtf(q*(1.f/128.f) + 1e-5f);
    float4 g4 = *(const float4*)&gam[cbase];
    float4 b4 = *(const float4*)&bet[cbase];
    *(float4*)&O[(size_t)n*DD + cbase] = make_float4(
        (v0-mu)*rstd*g4.x + b4.x, (v1-mu)*rstd*g4.y + b4.y,
        (v2-mu)*rstd*g4.z + b4.z, (v3-mu)*rstd*g4.w + b4.w);
}

// ---------------- launch ----------------
extern "C" void kernel_launch(void* const* d_in, const int* in_sizes, int n_in,
                              void* d_out, int out_size) {
    const float* x   = (const float*)d_in[0];
    const int*   ei  = (const int*)  d_in[1];
    const float* ea  = (const float*)d_in[2];
    const float* Wl  = (const float*)d_in[3];
    const float* bl  = (const float*)d_in[4];
    const float* Wr  = (const float*)d_in[5];
    const float* br  = (const float*)d_in[6];
    const float* We  = (const float*)d_in[7];
    const float* att = (const float*)d_in[8];
    const float* gb  = (const float*)d_in[9];
    const float* g1  = (const float*)d_in[10];
    const float* b1  = (const float*)d_in[11];
    const float* g2  = (const float*)d_in[12];
    const float* b2  = (const float*)d_in[13];
    const float* W1  = (const float*)d_in[14];
    const float* W2  = (const float*)d_in[15];

    float* out    = (float*)d_out;
    float* out_ei = out + (size_t)NN*DD;
    float* alpha  = out + (size_t)NN*DD + 2*(size_t)EN;

    const int T = 256;
    k_init<<<(EN + T-1)/T, T>>>(out_ei, ei);
    k_count<<<(EE + T-1)/T, T>>>(ei);
    k_scan<<<1, 1024>>>();
    k_scatter<<<(EE + T-1)/T, T>>>(ei);
    k_loopattr<<<(NN*32 + T-1)/T, T>>>(ea);

    int rowsN = (NN + 127)/128;
    sgemm<0,1,true,false><<<dim3(1, rowsN), 256>>>(x, Wl, bl, nullptr, NN, 128, 128);
    sgemm<0,2,true,false><<<dim3(1, rowsN), 256>>>(x, Wr, br, nullptr, NN, 128, 128);

    k_elogits<<<(EN + 127)/128, 256>>>(ei, ea, We, att, alpha);
    k_smagg<<<(NN*32 + T-1)/T, T>>>(x, gb, g1, b1, alpha);

    sgemm<6,7,false,true><<<dim3(2, rowsN), 256>>>(nullptr, W1, nullptr, nullptr, NN, 256, 128);
    sgemm<7,8,false,false><<<dim3(1, rowsN), 256>>>(nullptr, W2, nullptr, nullptr, NN, 128, 256);
    k_ln2<<<(NN*32 + T-1)/T, T>>>(g2, b2, out);
}

// round 4
// speedup vs baseline: 1.7639x; 1.0592x over previous
#include <cuda_runtime.h>
#include <math.h>

#define NN 50000
#define EE 640000
#define DD 128
#define EDIM 64
#define HH 4
#define HC 128
#define EN (EE+NN)

// ---------------- scratch (device globals; no allocation) ----------------
__device__ float g_xl[NN*HC];
__device__ float g_xr[NN*HC];
__device__ float g_loop[NN*EDIM];
__device__ float g_h[NN*DD];
__device__ float g_mid[NN*2*DD];
__device__ float g_mlp[NN*DD];
__device__ int   g_cnt[NN];
__device__ int   g_cur[NN];
__device__ int   g_off[NN+1];
__device__ int   g_srow[EE];
__device__ int   g_ssrc[EE];

template<int B> __device__ __forceinline__ float* bufsel(const float* ext){
    if constexpr (B==0) return const_cast<float*>(ext);
    else if constexpr (B==1) return g_xl;
    else if constexpr (B==2) return g_xr;
    else if constexpr (B==6) return g_h;
    else if constexpr (B==7) return g_mid;
    else return g_mlp;
}

// ---------------- packed f32x2 helpers ----------------
__device__ __forceinline__ unsigned long long pack2(float lo, float hi){
    unsigned long long r; asm("mov.b64 %0, {%1,%2};" : "=l"(r) : "f"(lo), "f"(hi)); return r;
}
__device__ __forceinline__ void unpack2(unsigned long long v, float& lo, float& hi){
    asm("mov.b64 {%0,%1}, %2;" : "=f"(lo), "=f"(hi) : "l"(v));
}
__device__ __forceinline__ void ffma2(unsigned long long &d, unsigned long long a, unsigned long long b){
    asm("fma.rn.f32x2 %0, %1, %2, %0;" : "+l"(d) : "l"(a), "l"(b));
}

// ---------------- init: zero counters + ei_sl output ----------------
__global__ void k_init(float* __restrict__ out_ei, const int* __restrict__ ei){
    int i = blockIdx.x*blockDim.x + threadIdx.x;
    if (i < NN) g_cnt[i] = 0;
    if (i < EN){
        int s = (i < EE) ? ei[i]     : (i-EE);
        int d = (i < EE) ? ei[EE+i]  : (i-EE);
        out_ei[i]    = (float)s;
        out_ei[EN+i] = (float)d;
    }
}

// ---------------- CSR build ----------------
__global__ void k_count(const int* __restrict__ ei){
    int i = blockIdx.x*blockDim.x + threadIdx.x;
    if (i < EE) atomicAdd(&g_cnt[ei[EE+i]], 1);
}

__global__ void k_scan(){
    __shared__ int part[1024];
    int t = threadIdx.x;
    const int chunk = (NN + 1023)/1024;
    int b = t*chunk;
    int sum = 0;
    for (int i = 0; i < chunk; i++){ int idx = b+i; if (idx < NN) sum += g_cnt[idx]; }
    part[t] = sum;
    __syncthreads();
    for (int off = 1; off < 1024; off <<= 1){
        int v = (t >= off) ? part[t-off] : 0;
        __syncthreads();
        part[t] += v;
        __syncthreads();
    }
    int run = (t == 0) ? 0 : part[t-1];
    for (int i = 0; i < chunk; i++){
        int idx = b+i;
        if (idx < NN){ g_off[idx] = run; g_cur[idx] = run; run += g_cnt[idx]; }
    }
    if (t == 1023) g_off[NN] = run;
}

__global__ void k_scatter(const int* __restrict__ ei){
    int i = blockIdx.x*blockDim.x + threadIdx.x;
    if (i >= EE) return;
    int d = ei[EE+i];
    int p = atomicAdd(&g_cur[d], 1);
    g_srow[p] = i;
    g_ssrc[p] = ei[i];
}

// ---------------- loop attr: CSR gather mean (warp per node, float2) ----------------
__global__ void k_loopattr(const float* __restrict__ ea){
    int t = blockIdx.x*blockDim.x + threadIdx.x;
    int n = t >> 5, lane = t & 31;
    if (n >= NN) return;
    int beg = g_off[n], end = g_off[n+1];
    float a0 = 0.f, a1 = 0.f;
    for (int idx = beg; idx < end; idx++){
        int row = g_srow[idx];
        float2 v = *(const float2*)&ea[(size_t)row*EDIM + lane*2];
        a0 += v.x; a1 += v.y;
    }
    float inv = 1.f / fmaxf((float)(end-beg), 1.f);
    *(float2*)&g_loop[(size_t)n*EDIM + lane*2] = make_float2(a0*inv, a1*inv);
}

// ---------------- SGEMM: C = A * B^T (+bias)(+gelu) ----------------
// 128x128 tile, BK=16, 256 threads, 8x8 microtile, f32x2, register-prefetch pipeline
template<int ABUF, int CBUF, bool BIAS, bool GELU>
__global__ __launch_bounds__(256, 2) void sgemm(
    const float* __restrict__ Aext, const float* __restrict__ Bw,
    const float* __restrict__ bias, float* __restrict__ Cext,
    int M, int Ncol, int K)
{
    const float* A = bufsel<ABUF>(Aext);
    float* C = bufsel<CBUF>((const float*)Cext);
    __shared__ float As[16][132];   // [k][m]
    __shared__ float Bs[16][132];   // [k][n]
    int tid = threadIdx.x;
    int tx = tid & 15, ty = tid >> 4;
    int row0 = blockIdx.y * 128, col0 = blockIdx.x * 128;
    int lm0 = tid >> 2,       lc0 = (tid & 3)*4;          // loader coords, i=0
    int lm1 = (tid+256) >> 2, lc1 = ((tid+256) & 3)*4;    // i=1

    unsigned long long acc[8][4];
    #pragma unroll
    for (int i=0;i<8;i++)
        #pragma unroll
        for (int j=0;j<4;j++) acc[i][j] = 0ULL;

    float4 pa0, pa1, pb0, pb1;
    {
        int gm0 = row0 + lm0, gm1 = row0 + lm1;
        pa0 = (gm0 < M) ? *(const float4*)&A[(size_t)gm0*K + lc0] : make_float4(0.f,0.f,0.f,0.f);
        pa1 = (gm1 < M) ? *(const float4*)&A[(size_t)gm1*K + lc1] : make_float4(0.f,0.f,0.f,0.f);
        pb0 = *(const float4*)&Bw[(size_t)(col0+lm0)*K + lc0];
        pb1 = *(const float4*)&Bw[(size_t)(col0+lm1)*K + lc1];
    }

    for (int k0 = 0; k0 < K; k0 += 16){
        As[lc0+0][lm0]=pa0.x; As[lc0+1][lm0]=pa0.y; As[lc0+2][lm0]=pa0.z; As[lc0+3][lm0]=pa0.w;
        As[lc1+0][lm1]=pa1.x; As[lc1+1][lm1]=pa1.y; As[lc1+2][lm1]=pa1.z; As[lc1+3][lm1]=pa1.w;
        Bs[lc0+0][lm0]=pb0.x; Bs[lc0+1][lm0]=pb0.y; Bs[lc0+2][lm0]=pb0.z; Bs[lc0+3][lm0]=pb0.w;
        Bs[lc1+0][lm1]=pb1.x; Bs[lc1+1][lm1]=pb1.y; Bs[lc1+2][lm1]=pb1.z; Bs[lc1+3][lm1]=pb1.w;
        __syncthreads();
        int kn = k0 + 16;
        if (kn < K){
            int gm0 = row0 + lm0, gm1 = row0 + lm1;
            pa0 = (gm0 < M) ? *(const float4*)&A[(size_t)gm0*K + kn + lc0] : make_float4(0.f,0.f,0.f,0.f);
            pa1 = (gm1 < M) ? *(const float4*)&A[(size_t)gm1*K + kn + lc1] : make_float4(0.f,0.f,0.f,0.f);
            pb0 = *(const float4*)&Bw[(size_t)(col0+lm0)*K + kn + lc0];
            pb1 = *(const float4*)&Bw[(size_t)(col0+lm1)*K + kn + lc1];
        }
        #pragma unroll
        for (int k = 0; k < 16; k++){
            float4 b0 = *(const float4*)&Bs[k][tx*8];
            float4 b1 = *(const float4*)&Bs[k][tx*8+4];
            unsigned long long bb[4];
            bb[0] = pack2(b0.x,b0.y); bb[1] = pack2(b0.z,b0.w);
            bb[2] = pack2(b1.x,b1.y); bb[3] = pack2(b1.z,b1.w);
            float4 a0 = *(const float4*)&As[k][ty*8];
            float4 a1 = *(const float4*)&As[k][ty*8+4];
            float ar[8] = {a0.x,a0.y,a0.z,a0.w,a1.x,a1.y,a1.z,a1.w};
            #pragma unroll
            for (int i=0;i<8;i++){
                unsigned long long a2 = pack2(ar[i], ar[i]);
                #pragma unroll
                for (int j=0;j<4;j++) ffma2(acc[i][j], a2, bb[j]);
            }
        }
        __syncthreads();
    }
    #pragma unroll
    for (int i=0;i<8;i++){
        int gm = row0 + ty*8 + i;
        if (gm >= M) continue;
        float v[8];
        #pragma unroll
        for (int j=0;j<4;j++) unpack2(acc[i][j], v[2*j], v[2*j+1]);
        int gn0 = col0 + tx*8;
        if (BIAS){
            float4 bsv0 = *(const float4*)&bias[gn0];
            float4 bsv1 = *(const float4*)&bias[gn0+4];
            v[0]+=bsv0.x; v[1]+=bsv0.y; v[2]+=bsv0.z; v[3]+=bsv0.w;
            v[4]+=bsv1.x; v[5]+=bsv1.y; v[6]+=bsv1.z; v[7]+=bsv1.w;
        }
        if (GELU){
            #pragma unroll
            for (int j=0;j<8;j++) v[j] = 0.5f*v[j]*(1.f + erff(v[j]*0.70710678118654752f));
        }
        *(float4*)&C[(size_t)gm*Ncol + gn0]     = make_float4(v[0],v[1],v[2],v[3]);
        *(float4*)&C[(size_t)gm*Ncol + gn0 + 4] = make_float4(v[4],v[5],v[6],v[7]);
    }
}

// ---------------- fused e-projection + attention logits ----------------
// 128 edges x 128 comps tile, K=64, 256 threads, 8x8 micro, f32x2, prefetch
__global__ __launch_bounds__(256, 2) void k_elogits(
    const int* __restrict__ ei, const float* __restrict__ ea,
    const float* __restrict__ We, const float* __restrict__ att,
    float* __restrict__ alpha)
{
    __shared__ float As[16][132];   // [k][edge]
    __shared__ float Bs[16][132];   // [k][comp]
    __shared__ int s_src[128], s_dst[128];
    int tid = threadIdx.x;
    int tx = tid & 15, ty = tid >> 4;
    int row0 = blockIdx.x * 128;
    int lm0 = tid >> 2,       lc0 = (tid & 3)*4;
    int lm1 = (tid+256) >> 2, lc1 = ((tid+256) & 3)*4;

    if (tid < 128){
        int e = row0 + tid;
        int s, d;
        if (e < EE){ s = ei[e]; d = ei[EE+e]; }
        else if (e < EN){ s = e-EE; d = e-EE; }
        else { s = 0; d = 0; }
        s_src[tid] = s; s_dst[tid] = d;
    }

    unsigned long long acc[8][4];
    #pragma unroll
    for (int i=0;i<8;i++)
        #pragma unroll
        for (int j=0;j<4;j++) acc[i][j] = 0ULL;

    auto loadA = [&](int m, int kc)->float4 {
        int eg = row0 + m;
        if (eg < EE)      return *(const float4*)&ea[(size_t)eg*EDIM + kc];
        else if (eg < EN) return *(const float4*)&g_loop[(size_t)(eg-EE)*EDIM + kc];
        else              return make_float4(0.f,0.f,0.f,0.f);
    };

    float4 pa0 = loadA(lm0, lc0);
    float4 pa1 = loadA(lm1, lc1);
    float4 pb0 = *(const float4*)&We[(size_t)lm0*EDIM + lc0];
    float4 pb1 = *(const float4*)&We[(size_t)lm1*EDIM + lc1];

    for (int k0 = 0; k0 < EDIM; k0 += 16){
        As[lc0+0][lm0]=pa0.x; As[lc0+1][lm0]=pa0.y; As[lc0+2][lm0]=pa0.z; As[lc0+3][lm0]=pa0.w;
        As[lc1+0][lm1]=pa1.x; As[lc1+1][lm1]=pa1.y; As[lc1+2][lm1]=pa1.z; As[lc1+3][lm1]=pa1.w;
        Bs[lc0+0][lm0]=pb0.x; Bs[lc0+1][lm0]=pb0.y; Bs[lc0+2][lm0]=pb0.z; Bs[lc0+3][lm0]=pb0.w;
        Bs[lc1+0][lm1]=pb1.x; Bs[lc1+1][lm1]=pb1.y; Bs[lc1+2][lm1]=pb1.z; Bs[lc1+3][lm1]=pb1.w;
        __syncthreads();
        int kn = k0 + 16;
        if (kn < EDIM){
            pa0 = loadA(lm0, kn + lc0);
            pa1 = loadA(lm1, kn + lc1);
            pb0 = *(const float4*)&We[(size_t)lm0*EDIM + kn + lc0];
            pb1 = *(const float4*)&We[(size_t)lm1*EDIM + kn + lc1];
        }
        #pragma unroll
        for (int k = 0; k < 16; k++){
            float4 b0 = *(const float4*)&Bs[k][tx*8];
            float4 b1 = *(const float4*)&Bs[k][tx*8+4];
            unsigned long long bb[4];
            bb[0] = pack2(b0.x,b0.y); bb[1] = pack2(b0.z,b0.w);
            bb[2] = pack2(b1.x,b1.y); bb[3] = pack2(b1.z,b1.w);
            float4 a0 = *(const float4*)&As[k][ty*8];
            float4 a1 = *(const float4*)&As[k][ty*8+4];
            float ar[8] = {a0.x,a0.y,a0.z,a0.w,a1.x,a1.y,a1.z,a1.w};
            #pragma unroll
            for (int i=0;i<8;i++){
                unsigned long long a2 = pack2(ar[i], ar[i]);
                #pragma unroll
                for (int j=0;j<4;j++) ffma2(acc[i][j], a2, bb[j]);
            }
        }
        __syncthreads();
    }

    int c0 = tx*8;
    float4 at0 = *(const float4*)&att[c0];
    float4 at1 = *(const float4*)&att[c0+4];
    float attv[8] = {at0.x,at0.y,at0.z,at0.w,at1.x,at1.y,at1.z,at1.w};
    int h = tx >> 2;
    bool writer = (tx & 3) == 0;

    #pragma unroll
    for (int i=0;i<8;i++){
        int el = ty*8 + i;
        int eg = row0 + el;
        int src = s_src[el], dst = s_dst[el];
        float4 xl0 = *(const float4*)&g_xl[(size_t)src*HC + c0];
        float4 xl1 = *(const float4*)&g_xl[(size_t)src*HC + c0 + 4];
        float4 xr0 = *(const float4*)&g_xr[(size_t)dst*HC + c0];
        float4 xr1 = *(const float4*)&g_xr[(size_t)dst*HC + c0 + 4];
        float xlr[8] = {xl0.x+xr0.x, xl0.y+xr0.y, xl0.z+xr0.z, xl0.w+xr0.w,
                        xl1.x+xr1.x, xl1.y+xr1.y, xl1.z+xr1.z, xl1.w+xr1.w};
        float v[8];
        #pragma unroll
        for (int j=0;j<4;j++) unpack2(acc[i][j], v[2*j], v[2*j+1]);
        float p = 0.f;
        #pragma unroll
        for (int j=0;j<8;j++){
            float gg = v[j] + xlr[j];
            gg = (gg > 0.f) ? gg : 0.2f*gg;
            p += gg * attv[j];
        }
        p += __shfl_xor_sync(0xffffffffu, p, 1);
        p += __shfl_xor_sync(0xffffffffu, p, 2);
        if (writer && eg < EN) alpha[(size_t)eg*4 + h] = p;
    }
}

// ---------------- online segment softmax + aggregate + residual + LN1 ----------------
__device__ __forceinline__ void online_upd(float l, float& m, float& s){
    if (l > m){ s = s*__expf(m-l) + 1.f; m = l; }
    else s += __expf(l-m);
}
__device__ __forceinline__ void online_merge(float om, float os, float& m, float& s){
    float nm = fmaxf(m, om);
    s = s*__expf(m-nm) + os*__expf(om-nm);
    m = nm;
}

__global__ void k_smagg(const float* __restrict__ x, const float* __restrict__ gbias,
                        const float* __restrict__ g1, const float* __restrict__ b1,
                        float* __restrict__ alpha)
{
    int t = blockIdx.x*blockDim.x + threadIdx.x;
    int n = t >> 5, lane = t & 31;
    if (n >= NN) return;
    int beg = g_off[n], end = g_off[n+1];
    float4* a4 = (float4*)alpha;

    float4 lsl = a4[EE+n];   // self-loop raw logits
    const float NEGBIG = -1e30f;
    float m0=NEGBIG,m1=NEGBIG,m2=NEGBIG,m3=NEGBIG;
    float s0=0.f,s1=0.f,s2=0.f,s3=0.f;
    for (int idx = beg + lane; idx < end; idx += 32){
        float4 l = a4[g_srow[idx]];
        online_upd(l.x, m0, s0); online_upd(l.y, m1, s1);
        online_upd(l.z, m2, s2); online_upd(l.w, m3, s3);
    }
    #pragma unroll
    for (int o = 16; o; o >>= 1){
        float om, os;
        om = __shfl_xor_sync(0xffffffffu, m0, o); os = __shfl_xor_sync(0xffffffffu, s0, o); online_merge(om, os, m0, s0);
        om = __shfl_xor_sync(0xffffffffu, m1, o); os = __shfl_xor_sync(0xffffffffu, s1, o); online_merge(om, os, m1, s1);
        om = __shfl_xor_sync(0xffffffffu, m2, o); os = __shfl_xor_sync(0xffffffffu, s2, o); online_merge(om, os, m2, s2);
        om = __shfl_xor_sync(0xffffffffu, m3, o); os = __shfl_xor_sync(0xffffffffu, s3, o); online_merge(om, os, m3, s3);
    }
    // self-loop contribution (identical on all lanes)
    online_upd(lsl.x, m0, s0); online_upd(lsl.y, m1, s1);
    online_upd(lsl.z, m2, s2); online_upd(lsl.w, m3, s3);

    float i0 = 1.f/s0, i1 = 1.f/s1, i2 = 1.f/s2, i3 = 1.f/s3;
    float asl0 = __expf(lsl.x - m0)*i0, asl1 = __expf(lsl.y - m1)*i1;
    float asl2 = __expf(lsl.z - m2)*i2, asl3 = __expf(lsl.w - m3)*i3;
    if (lane == 0) a4[EE+n] = make_float4(asl0, asl1, asl2, asl3);
    for (int idx = beg + lane; idx < end; idx += 32){
        int row = g_srow[idx];
        float4 l = a4[row];
        a4[row] = make_float4(__expf(l.x - m0)*i0, __expf(l.y - m1)*i1,
                              __expf(l.z - m2)*i2, __expf(l.w - m3)*i3);
    }
    __syncwarp();

    // aggregate: lane owns comps lane*4..lane*4+3 (head = lane/8)
    int cbase = lane*4;
    int h = lane >> 3;
    float4 accv = make_float4(0.f,0.f,0.f,0.f);
    for (int idx = beg; idx < end; idx++){
        int row = g_srow[idx], src = g_ssrc[idx];
        float4 a = a4[row];
        float ah = (h==0) ? a.x : (h==1) ? a.y : (h==2) ? a.z : a.w;
        float4 xv = *(const float4*)&g_xl[(size_t)src*HC + cbase];
        accv.x += ah*xv.x; accv.y += ah*xv.y; accv.z += ah*xv.z; accv.w += ah*xv.w;
    }
    {
        float ah = (h==0) ? asl0 : (h==1) ? asl1 : (h==2) ? asl2 : asl3;
        float4 xv = *(const float4*)&g_xl[(size_t)n*HC + cbase];
        accv.x += ah*xv.x; accv.y += ah*xv.y; accv.z += ah*xv.z; accv.w += ah*xv.w;
    }

    // residual + bias + LN1
    float4 xres = *(const float4*)&x[(size_t)n*DD + cbase];
    float4 gb4  = *(const float4*)&gbias[cbase];
    float v0 = accv.x + xres.x + gb4.x;
    float v1 = accv.y + xres.y + gb4.y;
    float v2 = accv.z + xres.z + gb4.z;
    float v3 = accv.w + xres.w + gb4.w;
    float s = v0+v1+v2+v3;
    #pragma unroll
    for (int o = 16; o; o >>= 1) s += __shfl_xor_sync(0xffffffffu, s, o);
    float mu = s * (1.f/128.f);
    float q = (v0-mu)*(v0-mu) + (v1-mu)*(v1-mu) + (v2-mu)*(v2-mu) + (v3-mu)*(v3-mu);
    #pragma unroll
    for (int o = 16; o; o >>= 1) q += __shfl_xor_sync(0xffffffffu, q, o);
    float rstd = rsqrtf(q*(1.f/128.f) + 1e-5f);
    float4 g14 = *(const float4*)&g1[cbase];
    float4 b14 = *(const float4*)&b1[cbase];
    *(float4*)&g_h[(size_t)n*DD + cbase] = make_float4(
        (v0-mu)*rstd*g14.x + b14.x, (v1-mu)*rstd*g14.y + b14.y,
        (v2-mu)*rstd*g14.z + b14.z, (v3-mu)*rstd*g14.w + b14.w);
}

// ---------------- residual + LayerNorm 2 (warp per node, float4) ----------------
__global__ void k_ln2(const float* __restrict__ gam, const float* __restrict__ bet,
                      float* __restrict__ O){
    int t = blockIdx.x*blockDim.x + threadIdx.x;
    int n = t >> 5, lane = t & 31;
    if (n >= NN) return;
    int cbase = lane*4;
    float4 hv = *(const float4*)&g_h[(size_t)n*DD + cbase];
    float4 mv = *(const float4*)&g_mlp[(size_t)n*DD + cbase];
    float v0 = hv.x+mv.x, v1 = hv.y+mv.y, v2 = hv.z+mv.z, v3 = hv.w+mv.w;
    float s = v0+v1+v2+v3;
    #pragma unroll
    for (int o=16;o;o>>=1) s += __shfl_xor_sync(0xffffffffu, s, o);
    float mu = s * (1.f/128.f);
    float q = (v0-mu)*(v0-mu) + (v1-mu)*(v1-mu) + (v2-mu)*(v2-mu) + (v3-mu)*(v3-mu);
    #pragma unroll
    for (int o=16;o;o>>=1) q += __shfl_xor_sync(0xffffffffu, q, o);
    float rstd = rsqrtf(q*(1.f/128.f) + 1e-5f);
    float4 g4 = *(const float4*)&gam[cbase];
    float4 b4 = *(const float4*)&bet[cbase];
    *(float4*)&O[(size_t)n*DD + cbase] = make_float4(
        (v0-mu)*rstd*g4.x + b4.x, (v1-mu)*rstd*g4.y + b4.y,
        (v2-mu)*rstd*g4.z + b4.z, (v3-mu)*rstd*g4.w + b4.w);
}

// ---------------- launch ----------------
extern "C" void kernel_launch(void* const* d_in, const int* in_sizes, int n_in,
                              void* d_out, int out_size) {
    const float* x   = (const float*)d_in[0];
    const int*   ei  = (const int*)  d_in[1];
    const float* ea  = (const float*)d_in[2];
    const float* Wl  = (const float*)d_in[3];
    const float* bl  = (const float*)d_in[4];
    const float* Wr  = (const float*)d_in[5];
    const float* br  = (const float*)d_in[6];
    const float* We  = (const float*)d_in[7];
    const float* att = (const float*)d_in[8];
    const float* gb  = (const float*)d_in[9];
    const float* g1  = (const float*)d_in[10];
    const float* b1  = (const float*)d_in[11];
    const float* g2  = (const float*)d_in[12];
    const float* b2  = (const float*)d_in[13];
    const float* W1  = (const float*)d_in[14];
    const float* W2  = (const float*)d_in[15];

    float* out    = (float*)d_out;
    float* out_ei = out + (size_t)NN*DD;
    float* alpha  = out + (size_t)NN*DD + 2*(size_t)EN;

    const int T = 256;
    k_init<<<(EN + T-1)/T, T>>>(out_ei, ei);
    k_count<<<(EE + T-1)/T, T>>>(ei);
    k_scan<<<1, 1024>>>();
    k_scatter<<<(EE + T-1)/T, T>>>(ei);
    k_loopattr<<<(NN*32 + T-1)/T, T>>>(ea);

    int rowsN = (NN + 127)/128;
    sgemm<0,1,true,false><<<dim3(1, rowsN), 256>>>(x, Wl, bl, nullptr, NN, 128, 128);
    sgemm<0,2,true,false><<<dim3(1, rowsN), 256>>>(x, Wr, br, nullptr, NN, 128, 128);

    k_elogits<<<(EN + 127)/128, 256>>>(ei, ea, We, att, alpha);
    k_smagg<<<(NN*32 + T-1)/T, T>>>(x, gb, g1, b1, alpha);

    sgemm<6,7,false,true><<<dim3(2, rowsN), 256>>>(nullptr, W1, nullptr, nullptr, NN, 256, 128);
    sgemm<7,8,false,false><<<dim3(1, rowsN), 256>>>(nullptr, W2, nullptr, nullptr, NN, 128, 256);
    k_ln2<<<(NN*32 + T-1)/T, T>>>(g2, b2, out);
}

// round 6
// speedup vs baseline: 1.8944x; 1.0740x over previous
#include <cuda_runtime.h>
#include <cuda_bf16.h>
#include <math.h>
#include <stdint.h>

#define NN 50000
#define EE 640000
#define DD 128
#define EDIM 64
#define HH 4
#define HC 128
#define EN (EE+NN)

// ---------------- scratch (device globals; no allocation) ----------------
__device__ float g_xl[NN*HC];
__device__ float g_xr[NN*HC];
__device__ float g_loop[NN*EDIM];
__device__ float g_h[NN*DD];
__device__ float g_mid[NN*2*DD];
__device__ float g_mlp[NN*DD];
__device__ int   g_cnt[NN];
__device__ int   g_cur[NN];
__device__ int   g_off[NN+1];
__device__ int   g_srow[EE];
__device__ int   g_ssrc[EE];

template<int B> __device__ __forceinline__ float* bufsel(const float* ext){
    if constexpr (B==0) return const_cast<float*>(ext);
    else if constexpr (B==1) return g_xl;
    else if constexpr (B==2) return g_xr;
    else if constexpr (B==6) return g_h;
    else if constexpr (B==7) return g_mid;
    else return g_mlp;
}

// ---------------- packed f32x2 helpers ----------------
__device__ __forceinline__ unsigned long long pack2(float lo, float hi){
    unsigned long long r; asm("mov.b64 %0, {%1,%2};" : "=l"(r) : "f"(lo), "f"(hi)); return r;
}
__device__ __forceinline__ void unpack2(unsigned long long v, float& lo, float& hi){
    asm("mov.b64 {%0,%1}, %2;" : "=f"(lo), "=f"(hi) : "l"(v));
}
__device__ __forceinline__ void ffma2(unsigned long long &d, unsigned long long a, unsigned long long b){
    asm("fma.rn.f32x2 %0, %1, %2, %0;" : "+l"(d) : "l"(a), "l"(b));
}

// ---------------- bf16 split helpers ----------------
__device__ __forceinline__ uint32_t bf16x2_of(float lo_elem, float hi_elem){
    uint32_t r; asm("cvt.rn.bf16x2.f32 %0, %1, %2;" : "=r"(r) : "f"(hi_elem), "f"(lo_elem)); return r;
}
__device__ __forceinline__ float2 bf16x2_back(uint32_t p){
    return make_float2(__uint_as_float(p << 16), __uint_as_float(p & 0xffff0000u));
}
// convert 2 floats -> (hi bf16x2, lo bf16x2)
__device__ __forceinline__ void split2(float x, float y, uint32_t& h, uint32_t& l){
    h = bf16x2_of(x, y);
    float2 hb = bf16x2_back(h);
    l = bf16x2_of(x - hb.x, y - hb.y);
}

__device__ __forceinline__ uint32_t smem_u32(const void* p){
    uint32_t a;
    asm("{ .reg .u64 t; cvta.to.shared.u64 t, %1; cvt.u32.u64 %0, t; }" : "=r"(a) : "l"(p));
    return a;
}

__device__ __forceinline__ void ldsm_x4(uint32_t* r, uint32_t addr){
    asm volatile("ldmatrix.sync.aligned.m8n8.x4.shared.b16 {%0,%1,%2,%3}, [%4];"
        : "=r"(r[0]), "=r"(r[1]), "=r"(r[2]), "=r"(r[3]) : "r"(addr));
}
__device__ __forceinline__ void mma16816(float* c, const uint32_t* a, uint32_t b0, uint32_t b1){
    asm volatile("mma.sync.aligned.m16n8k16.row.col.f32.bf16.bf16.f32 "
        "{%0,%1,%2,%3}, {%4,%5,%6,%7}, {%8,%9}, {%0,%1,%2,%3};"
        : "+f"(c[0]), "+f"(c[1]), "+f"(c[2]), "+f"(c[3])
        : "r"(a[0]), "r"(a[1]), "r"(a[2]), "r"(a[3]), "r"(b0), "r"(b1));
}

// ---------------- init: zero counters + ei_sl output ----------------
__global__ void k_init(float* __restrict__ out_ei, const int* __restrict__ ei){
    int i = blockIdx.x*blockDim.x + threadIdx.x;
    if (i < NN) g_cnt[i] = 0;
    if (i < EN){
        int s = (i < EE) ? ei[i]     : (i-EE);
        int d = (i < EE) ? ei[EE+i]  : (i-EE);
        out_ei[i]    = (float)s;
        out_ei[EN+i] = (float)d;
    }
}

// ---------------- CSR build ----------------
__global__ void k_count(const int* __restrict__ ei){
    int i = blockIdx.x*blockDim.x + threadIdx.x;
    if (i < EE) atomicAdd(&g_cnt[ei[EE+i]], 1);
}

__global__ void k_scan(){
    __shared__ int part[1024];
    int t = threadIdx.x;
    const int chunk = (NN + 1023)/1024;
    int b = t*chunk;
    int sum = 0;
    for (int i = 0; i < chunk; i++){ int idx = b+i; if (idx < NN) sum += g_cnt[idx]; }
    part[t] = sum;
    __syncthreads();
    for (int off = 1; off < 1024; off <<= 1){
        int v = (t >= off) ? part[t-off] : 0;
        __syncthreads();
        part[t] += v;
        __syncthreads();
    }
    int run = (t == 0) ? 0 : part[t-1];
    for (int i = 0; i < chunk; i++){
        int idx = b+i;
        if (idx < NN){ g_off[idx] = run; g_cur[idx] = run; run += g_cnt[idx]; }
    }
    if (t == 1023) g_off[NN] = run;
}

__global__ void k_scatter(const int* __restrict__ ei){
    int i = blockIdx.x*blockDim.x + threadIdx.x;
    if (i >= EE) return;
    int d = ei[EE+i];
    int p = atomicAdd(&g_cur[d], 1);
    g_srow[p] = i;
    g_ssrc[p] = ei[i];
}

// ---------------- loop attr: CSR gather mean (warp per node, float2) ----------------
__global__ void k_loopattr(const float* __restrict__ ea){
    int t = blockIdx.x*blockDim.x + threadIdx.x;
    int n = t >> 5, lane = t & 31;
    if (n >= NN) return;
    int beg = g_off[n], end = g_off[n+1];
    float a0 = 0.f, a1 = 0.f;
    for (int idx = beg; idx < end; idx++){
        int row = g_srow[idx];
        float2 v = *(const float2*)&ea[(size_t)row*EDIM + lane*2];
        a0 += v.x; a1 += v.y;
    }
    float inv = 1.f / fmaxf((float)(end-beg), 1.f);
    *(float2*)&g_loop[(size_t)n*EDIM + lane*2] = make_float2(a0*inv, a1*inv);
}

// ---------------- SGEMM: C = A * B^T (+bias)(+gelu) ----------------
// 128x128 tile, BK=16, 256 threads, 8x8 microtile, f32x2, register-prefetch pipeline
template<int ABUF, int CBUF, bool BIAS, bool GELU>
__global__ __launch_bounds__(256, 2) void sgemm(
    const float* __restrict__ Aext, const float* __restrict__ Bw,
    const float* __restrict__ bias, float* __restrict__ Cext,
    int M, int Ncol, int K)
{
    const float* A = bufsel<ABUF>(Aext);
    float* C = bufsel<CBUF>((const float*)Cext);
    __shared__ float As[16][132];
    __shared__ float Bs[16][132];
    int tid = threadIdx.x;
    int tx = tid & 15, ty = tid >> 4;
    int row0 = blockIdx.y * 128, col0 = blockIdx.x * 128;
    int lm0 = tid >> 2,       lc0 = (tid & 3)*4;
    int lm1 = (tid+256) >> 2, lc1 = ((tid+256) & 3)*4;

    unsigned long long acc[8][4];
    #pragma unroll
    for (int i=0;i<8;i++)
        #pragma unroll
        for (int j=0;j<4;j++) acc[i][j] = 0ULL;

    float4 pa0, pa1, pb0, pb1;
    {
        int gm0 = row0 + lm0, gm1 = row0 + lm1;
        pa0 = (gm0 < M) ? *(const float4*)&A[(size_t)gm0*K + lc0] : make_float4(0.f,0.f,0.f,0.f);
        pa1 = (gm1 < M) ? *(const float4*)&A[(size_t)gm1*K + lc1] : make_float4(0.f,0.f,0.f,0.f);
        pb0 = *(const float4*)&Bw[(size_t)(col0+lm0)*K + lc0];
        pb1 = *(const float4*)&Bw[(size_t)(col0+lm1)*K + lc1];
    }

    for (int k0 = 0; k0 < K; k0 += 16){
        As[lc0+0][lm0]=pa0.x; As[lc0+1][lm0]=pa0.y; As[lc0+2][lm0]=pa0.z; As[lc0+3][lm0]=pa0.w;
        As[lc1+0][lm1]=pa1.x; As[lc1+1][lm1]=pa1.y; As[lc1+2][lm1]=pa1.z; As[lc1+3][lm1]=pa1.w;
        Bs[lc0+0][lm0]=pb0.x; Bs[lc0+1][lm0]=pb0.y; Bs[lc0+2][lm0]=pb0.z; Bs[lc0+3][lm0]=pb0.w;
        Bs[lc1+0][lm1]=pb1.x; Bs[lc1+1][lm1]=pb1.y; Bs[lc1+2][lm1]=pb1.z; Bs[lc1+3][lm1]=pb1.w;
        __syncthreads();
        int kn = k0 + 16;
        if (kn < K){
            int gm0 = row0 + lm0, gm1 = row0 + lm1;
            pa0 = (gm0 < M) ? *(const float4*)&A[(size_t)gm0*K + kn + lc0] : make_float4(0.f,0.f,0.f,0.f);
            pa1 = (gm1 < M) ? *(const float4*)&A[(size_t)gm1*K + kn + lc1] : make_float4(0.f,0.f,0.f,0.f);
            pb0 = *(const float4*)&Bw[(size_t)(col0+lm0)*K + kn + lc0];
            pb1 = *(const float4*)&Bw[(size_t)(col0+lm1)*K + kn + lc1];
        }
        #pragma unroll
        for (int k = 0; k < 16; k++){
            float4 b0 = *(const float4*)&Bs[k][tx*8];
            float4 b1 = *(const float4*)&Bs[k][tx*8+4];
            unsigned long long bb[4];
            bb[0] = pack2(b0.x,b0.y); bb[1] = pack2(b0.z,b0.w);
            bb[2] = pack2(b1.x,b1.y); bb[3] = pack2(b1.z,b1.w);
            float4 a0 = *(const float4*)&As[k][ty*8];
            float4 a1 = *(const float4*)&As[k][ty*8+4];
            float ar[8] = {a0.x,a0.y,a0.z,a0.w,a1.x,a1.y,a1.z,a1.w};
            #pragma unroll
            for (int i=0;i<8;i++){
                unsigned long long a2 = pack2(ar[i], ar[i]);
                #pragma unroll
                for (int j=0;j<4;j++) ffma2(acc[i][j], a2, bb[j]);
            }
        }
        __syncthreads();
    }
    #pragma unroll
    for (int i=0;i<8;i++){
        int gm = row0 + ty*8 + i;
        if (gm >= M) continue;
        float v[8];
        #pragma unroll
        for (int j=0;j<4;j++) unpack2(acc[i][j], v[2*j], v[2*j+1]);
        int gn0 = col0 + tx*8;
        if (BIAS){
            float4 bsv0 = *(const float4*)&bias[gn0];
            float4 bsv1 = *(const float4*)&bias[gn0+4];
            v[0]+=bsv0.x; v[1]+=bsv0.y; v[2]+=bsv0.z; v[3]+=bsv0.w;
            v[4]+=bsv1.x; v[5]+=bsv1.y; v[6]+=bsv1.z; v[7]+=bsv1.w;
        }
        if (GELU){
            #pragma unroll
            for (int j=0;j<8;j++) v[j] = 0.5f*v[j]*(1.f + erff(v[j]*0.70710678118654752f));
        }
        *(float4*)&C[(size_t)gm*Ncol + gn0]     = make_float4(v[0],v[1],v[2],v[3]);
        *(float4*)&C[(size_t)gm*Ncol + gn0 + 4] = make_float4(v[4],v[5],v[6],v[7]);
    }
}

// ---------------- fused e-projection + logits via mma.sync bf16-split ----------------
// Tile: 128 edges (M) x 128 comps (N), K=64 fp32 split hi/lo bf16.
// D = Ah·Bh^T + Ah·Bl^T + Al·Bh^T (fp32 accum). 8 warps; warp w owns rows w*16..w*16+15.
// smem rows padded to 72 bf16 (144B) so ldmatrix row pointers are bank-conflict-free.
#define EL_STRIDE 72
#define EL_BUF (128*EL_STRIDE*2)          // 18432 B per buffer
#define EL_SMEM_BYTES (4*EL_BUF)          // 73728 B

__global__ __launch_bounds__(256) void k_elogits_hmma(
    const int* __restrict__ ei, const float* __restrict__ ea,
    const float* __restrict__ We, const float* __restrict__ att,
    float* __restrict__ alpha)
{
    extern __shared__ __align__(16) uint8_t dynsmem[];
    __shared__ int s_src[128], s_dst[128];
    __shared__ float s_att[128];

    uint16_t* Ah = (uint16_t*)(dynsmem);
    uint16_t* Al = (uint16_t*)(dynsmem + EL_BUF);
    uint16_t* Bh = (uint16_t*)(dynsmem + 2*EL_BUF);
    uint16_t* Bl = (uint16_t*)(dynsmem + 3*EL_BUF);

    int tid = threadIdx.x;
    int w = tid >> 5, lane = tid & 31;
    int row0 = blockIdx.x * 128;

    if (tid < 128){
        int e = row0 + tid;
        int s, d;
        if (e < EE){ s = ei[e]; d = ei[EE+e]; }
        else if (e < EN){ s = e-EE; d = e-EE; }
        else { s = 0; d = 0; }
        s_src[tid] = s; s_dst[tid] = d;
        s_att[tid] = att[tid];
    }

    // ---- convert phase: thread handles row tid>>1, 32-col half tid&1 ----
    {
        int row = tid >> 1, half = tid & 1;
        int cb = half*32;
        // A row
        int eg = row0 + row;
        const float* arow = nullptr;
        bool zero = false;
        if (eg < EE)      arow = &ea[(size_t)eg*EDIM + cb];
        else if (eg < EN) arow = &g_loop[(size_t)(eg-EE)*EDIM + cb];
        else              zero = true;
        const float* brow = &We[(size_t)row*EDIM + cb];
        #pragma unroll
        for (int q = 0; q < 8; q++){
            int col = cb + q*4;
            uint32_t h0, l0, h1, l1;
            if (zero){ h0=l0=h1=l1=0u; }
            else {
                float4 v = *(const float4*)&arow[q*4];
                split2(v.x, v.y, h0, l0);
                split2(v.z, v.w, h1, l1);
            }
            *(uint2*)&Ah[row*EL_STRIDE + col] = make_uint2(h0, h1);
            *(uint2*)&Al[row*EL_STRIDE + col] = make_uint2(l0, l1);
            {
                float4 v = *(const float4*)&brow[q*4];
                uint32_t bh0, bl0, bh1, bl1;
                split2(v.x, v.y, bh0, bl0);
                split2(v.z, v.w, bh1, bl1);
                *(uint2*)&Bh[row*EL_STRIDE + col] = make_uint2(bh0, bh1);
                *(uint2*)&Bl[row*EL_STRIDE + col] = make_uint2(bl0, bl1);
            }
        }
    }
    __syncthreads();

    // ---- MMA phase ----
    int m0 = w*16;
    float acc[16][4];
    #pragma unroll
    for (int j=0;j<16;j++){ acc[j][0]=0.f; acc[j][1]=0.f; acc[j][2]=0.f; acc[j][3]=0.f; }

    // A lane address pieces
    int arow_l = m0 + (lane & 15);
    int akoff  = (lane >> 4) * 8;
    uint32_t addrAh = smem_u32(Ah) + (arow_l*EL_STRIDE + akoff)*2;
    uint32_t addrAl = smem_u32(Al) + (arow_l*EL_STRIDE + akoff)*2;
    // B lane address pieces (pair of n-tiles per ldmatrix.x4)
    int brow_l = (lane & 7) + ((lane >> 4) << 3);   // 0..15 within a 16-row n-pair
    int bkoff  = ((lane >> 3) & 1) * 8;
    uint32_t addrBh = smem_u32(Bh) + (brow_l*EL_STRIDE + bkoff)*2;
    uint32_t addrBl = smem_u32(Bl) + (brow_l*EL_STRIDE + bkoff)*2;

    #pragma unroll
    for (int kk = 0; kk < 4; kk++){
        uint32_t kofs = (kk*16)*2;
        uint32_t ah[4], al[4];
        ldsm_x4(ah, addrAh + kofs);
        ldsm_x4(al, addrAl + kofs);
        #pragma unroll
        for (int jj = 0; jj < 8; jj++){
            uint32_t bofs = (jj*16*EL_STRIDE)*2 + kofs;
            uint32_t bh[4], bl[4];
            ldsm_x4(bh, addrBh + bofs);
            ldsm_x4(bl, addrBl + bofs);
            mma16816(acc[2*jj],   ah, bh[0], bh[1]);
            mma16816(acc[2*jj+1], ah, bh[2], bh[3]);
            mma16816(acc[2*jj],   ah, bl[0], bl[1]);
            mma16816(acc[2*jj+1], ah, bl[2], bl[3]);
            mma16816(acc[2*jj],   al, bh[0], bh[1]);
            mma16816(acc[2*jj+1], al, bh[2], bh[3]);
        }
    }

    // ---- epilogue on fragment layout ----
    int qid = lane >> 2;
    int r0 = m0 + qid, r1 = r0 + 8;
    int eg0 = row0 + r0, eg1 = row0 + r1;
    int sA = s_src[r0], dA = s_dst[r0];
    int sB = s_src[r1], dB = s_dst[r1];
    const float* xlA = g_xl + (size_t)sA*HC;
    const float* xrA = g_xr + (size_t)dA*HC;
    const float* xlB = g_xl + (size_t)sB*HC;
    const float* xrB = g_xr + (size_t)dB*HC;
    int cbase = (lane & 3)*2;
    float p0[4] = {0.f,0.f,0.f,0.f};
    float p1[4] = {0.f,0.f,0.f,0.f};
    #pragma unroll
    for (int j = 0; j < 16; j++){
        int c = j*8 + cbase;
        int head = j >> 2;
        float2 xl0 = *(const float2*)&xlA[c];
        float2 xr0 = *(const float2*)&xrA[c];
        float2 xl1 = *(const float2*)&xlB[c];
        float2 xr1 = *(const float2*)&xrB[c];
        float a0 = s_att[c], a1 = s_att[c+1];
        float v;
        v = acc[j][0] + xl0.x + xr0.x; v = (v>0.f)?v:0.2f*v; p0[head] += v*a0;
        v = acc[j][1] + xl0.y + xr0.y; v = (v>0.f)?v:0.2f*v; p0[head] += v*a1;
        v = acc[j][2] + xl1.x + xr1.x; v = (v>0.f)?v:0.2f*v; p1[head] += v*a0;
        v = acc[j][3] + xl1.y + xr1.y; v = (v>0.f)?v:0.2f*v; p1[head] += v*a1;
    }
    #pragma unroll
    for (int o = 1; o <= 2; o <<= 1){
        #pragma unroll
        for (int hh = 0; hh < 4; hh++){
            p0[hh] += __shfl_xor_sync(0xffffffffu, p0[hh], o);
            p1[hh] += __shfl_xor_sync(0xffffffffu, p1[hh], o);
        }
    }
    if ((lane & 3) == 0){
        if (eg0 < EN) *(float4*)&alpha[(size_t)eg0*4] = make_float4(p0[0], p0[1], p0[2], p0[3]);
        if (eg1 < EN) *(float4*)&alpha[(size_t)eg1*4] = make_float4(p1[0], p1[1], p1[2], p1[3]);
    }
}

// ---------------- online segment softmax + aggregate + residual + LN1 ----------------
__device__ __forceinline__ void online_upd(float l, float& m, float& s){
    if (l > m){ s = s*__expf(m-l) + 1.f; m = l; }
    else s += __expf(l-m);
}
__device__ __forceinline__ void online_merge(float om, float os, float& m, float& s){
    float nm = fmaxf(m, om);
    s = s*__expf(m-nm) + os*__expf(om-nm);
    m = nm;
}

__global__ void k_smagg(const float* __restrict__ x, const float* __restrict__ gbias,
                        const float* __restrict__ g1, const float* __restrict__ b1,
                        float* __restrict__ alpha)
{
    int t = blockIdx.x*blockDim.x + threadIdx.x;
    int n = t >> 5, lane = t & 31;
    if (n >= NN) return;
    int beg = g_off[n], end = g_off[n+1];
    float4* a4 = (float4*)alpha;

    float4 lsl = a4[EE+n];
    const float NEGBIG = -1e30f;
    float m0=NEGBIG,m1=NEGBIG,m2=NEGBIG,m3=NEGBIG;
    float s0=0.f,s1=0.f,s2=0.f,s3=0.f;
    for (int idx = beg + lane; idx < end; idx += 32){
        float4 l = a4[g_srow[idx]];
        online_upd(l.x, m0, s0); online_upd(l.y, m1, s1);
        online_upd(l.z, m2, s2); online_upd(l.w, m3, s3);
    }
    #pragma unroll
    for (int o = 16; o; o >>= 1){
        float om, os;
        om = __shfl_xor_sync(0xffffffffu, m0, o); os = __shfl_xor_sync(0xffffffffu, s0, o); online_merge(om, os, m0, s0);
        om = __shfl_xor_sync(0xffffffffu, m1, o); os = __shfl_xor_sync(0xffffffffu, s1, o); online_merge(om, os, m1, s1);
        om = __shfl_xor_sync(0xffffffffu, m2, o); os = __shfl_xor_sync(0xffffffffu, s2, o); online_merge(om, os, m2, s2);
        om = __shfl_xor_sync(0xffffffffu, m3, o); os = __shfl_xor_sync(0xffffffffu, s3, o); online_merge(om, os, m3, s3);
    }
    online_upd(lsl.x, m0, s0); online_upd(lsl.y, m1, s1);
    online_upd(lsl.z, m2, s2); online_upd(lsl.w, m3, s3);

    float i0 = 1.f/s0, i1 = 1.f/s1, i2 = 1.f/s2, i3 = 1.f/s3;
    float asl0 = __expf(lsl.x - m0)*i0, asl1 = __expf(lsl.y - m1)*i1;
    float asl2 = __expf(lsl.z - m2)*i2, asl3 = __expf(lsl.w - m3)*i3;
    if (lane == 0) a4[EE+n] = make_float4(asl0, asl1, asl2, asl3);
    for (int idx = beg + lane; idx < end; idx += 32){
        int row = g_srow[idx];
        float4 l = a4[row];
        a4[row] = make_float4(__expf(l.x - m0)*i0, __expf(l.y - m1)*i1,
                              __expf(l.z - m2)*i2, __expf(l.w - m3)*i3);
    }
    __syncwarp();

    int cbase = lane*4;
    int h = lane >> 3;
    float4 accv = make_float4(0.f,0.f,0.f,0.f);
    for (int idx = beg; idx < end; idx++){
        int row = g_srow[idx], src = g_ssrc[idx];
        float4 a = a4[row];
        float ah = (h==0) ? a.x : (h==1) ? a.y : (h==2) ? a.z : a.w;
        float4 xv = *(const float4*)&g_xl[(size_t)src*HC + cbase];
        accv.x += ah*xv.x; accv.y += ah*xv.y; accv.z += ah*xv.z; accv.w += ah*xv.w;
    }
    {
        float ah = (h==0) ? asl0 : (h==1) ? asl1 : (h==2) ? asl2 : asl3;
        float4 xv = *(const float4*)&g_xl[(size_t)n*HC + cbase];
        accv.x += ah*xv.x; accv.y += ah*xv.y; accv.z += ah*xv.z; accv.w += ah*xv.w;
    }

    float4 xres = *(const float4*)&x[(size_t)n*DD + cbase];
    float4 gb4  = *(const float4*)&gbias[cbase];
    float v0 = accv.x + xres.x + gb4.x;
    float v1 = accv.y + xres.y + gb4.y;
    float v2 = accv.z + xres.z + gb4.z;
    float v3 = accv.w + xres.w + gb4.w;
    float s = v0+v1+v2+v3;
    #pragma unroll
    for (int o = 16; o; o >>= 1) s += __shfl_xor_sync(0xffffffffu, s, o);
    float mu = s * (1.f/128.f);
    float q = (v0-mu)*(v0-mu) + (v1-mu)*(v1-mu) + (v2-mu)*(v2-mu) + (v3-mu)*(v3-mu);
    #pragma unroll
    for (int o = 16; o; o >>= 1) q += __shfl_xor_sync(0xffffffffu, q, o);
    float rstd = rsqrtf(q*(1.f/128.f) + 1e-5f);
    float4 g14 = *(const float4*)&g1[cbase];
    float4 b14 = *(const float4*)&b1[cbase];
    *(float4*)&g_h[(size_t)n*DD + cbase] = make_float4(
        (v0-mu)*rstd*g14.x + b14.x, (v1-mu)*rstd*g14.y + b14.y,
        (v2-mu)*rstd*g14.z + b14.z, (v3-mu)*rstd*g14.w + b14.w);
}

// ---------------- residual + LayerNorm 2 (warp per node, float4) ----------------
__global__ void k_ln2(const float* __restrict__ gam, const float* __restrict__ bet,
                      float* __restrict__ O){
    int t = blockIdx.x*blockDim.x + threadIdx.x;
    int n = t >> 5, lane = t & 31;
    if (n >= NN) return;
    int cbase = lane*4;
    float4 hv = *(const float4*)&g_h[(size_t)n*DD + cbase];
    float4 mv = *(const float4*)&g_mlp[(size_t)n*DD + cbase];
    float v0 = hv.x+mv.x, v1 = hv.y+mv.y, v2 = hv.z+mv.z, v3 = hv.w+mv.w;
    float s = v0+v1+v2+v3;
    #pragma unroll
    for (int o=16;o;o>>=1) s += __shfl_xor_sync(0xffffffffu, s, o);
    float mu = s * (1.f/128.f);
    float q = (v0-mu)*(v0-mu) + (v1-mu)*(v1-mu) + (v2-mu)*(v2-mu) + (v3-mu)*(v3-mu);
    #pragma unroll
    for (int o=16;o;o>>=1) q += __shfl_xor_sync(0xffffffffu, q, o);
    float rstd = rsqrtf(q*(1.f/128.f) + 1e-5f);
    float4 g4 = *(const float4*)&gam[cbase];
    float4 b4 = *(const float4*)&bet[cbase];
    *(float4*)&O[(size_t)n*DD + cbase] = make_float4(
        (v0-mu)*rstd*g4.x + b4.x, (v1-mu)*rstd*g4.y + b4.y,
        (v2-mu)*rstd*g4.z + b4.z, (v3-mu)*rstd*g4.w + b4.w);
}

// ---------------- launch ----------------
extern "C" void kernel_launch(void* const* d_in, const int* in_sizes, int n_in,
                              void* d_out, int out_size) {
    const float* x   = (const float*)d_in[0];
    const int*   ei  = (const int*)  d_in[1];
    const float* ea  = (const float*)d_in[2];
    const float* Wl  = (const float*)d_in[3];
    const float* bl  = (const float*)d_in[4];
    const float* Wr  = (const float*)d_in[5];
    const float* br  = (const float*)d_in[6];
    const float* We  = (const float*)d_in[7];
    const float* att = (const float*)d_in[8];
    const float* gb  = (const float*)d_in[9];
    const float* g1  = (const float*)d_in[10];
    const float* b1  = (const float*)d_in[11];
    const float* g2  = (const float*)d_in[12];
    const float* b2  = (const float*)d_in[13];
    const float* W1  = (const float*)d_in[14];
    const float* W2  = (const float*)d_in[15];

    float* out    = (float*)d_out;
    float* out_ei = out + (size_t)NN*DD;
    float* alpha  = out + (size_t)NN*DD + 2*(size_t)EN;

    cudaFuncSetAttribute(k_elogits_hmma, cudaFuncAttributeMaxDynamicSharedMemorySize, EL_SMEM_BYTES);

    const int T = 256;
    k_init<<<(EN + T-1)/T, T>>>(out_ei, ei);
    k_count<<<(EE + T-1)/T, T>>>(ei);
    k_scan<<<1, 1024>>>();
    k_scatter<<<(EE + T-1)/T, T>>>(ei);
    k_loopattr<<<(NN*32 + T-1)/T, T>>>(ea);

    int rowsN = (NN + 127)/128;
    sgemm<0,1,true,false><<<dim3(1, rowsN), 256>>>(x, Wl, bl, nullptr, NN, 128, 128);
    sgemm<0,2,true,false><<<dim3(1, rowsN), 256>>>(x, Wr, br, nullptr, NN, 128, 128);

    k_elogits_hmma<<<(EN + 127)/128, 256, EL_SMEM_BYTES>>>(ei, ea, We, att, alpha);
    k_smagg<<<(NN*32 + T-1)/T, T>>>(x, gb, g1, b1, alpha);

    sgemm<6,7,false,true><<<dim3(2, rowsN), 256>>>(nullptr, W1, nullptr, nullptr, NN, 256, 128);
    sgemm<7,8,false,false><<<dim3(1, rowsN), 256>>>(nullptr, W2, nullptr, nullptr, NN, 128, 256);
    k_ln2<<<(NN*32 + T-1)/T, T>>>(g2, b2, out);
}

// round 7
// speedup vs baseline: 2.1281x; 1.1233x over previous
#include <cuda_runtime.h>
#include <cuda_bf16.h>
#include <math.h>
#include <stdint.h>

#define NN 50000
#define EE 640000
#define DD 128
#define EDIM 64
#define HH 4
#define HC 128
#define EN (EE+NN)

// ---------------- scratch (device globals; no allocation) ----------------
__device__ float g_xl[NN*HC];
__device__ float g_xr[NN*HC];
__device__ float g_loop[NN*EDIM];
__device__ float g_h[NN*DD];
__device__ float g_mid[NN*2*DD];
__device__ float g_mlp[NN*DD];
__device__ int   g_cnt[NN];
__device__ int   g_cur[NN];
__device__ int   g_off[NN+1];
__device__ int   g_srow[EE];
__device__ int   g_ssrc[EE];

template<int B> __device__ __forceinline__ float* bufsel(const float* ext){
    if constexpr (B==0) return const_cast<float*>(ext);
    else if constexpr (B==1) return g_xl;
    else if constexpr (B==2) return g_xr;
    else if constexpr (B==6) return g_h;
    else if constexpr (B==7) return g_mid;
    else return g_mlp;
}

// ---------------- bf16 split helpers ----------------
__device__ __forceinline__ uint32_t bf16x2_of(float lo_elem, float hi_elem){
    uint32_t r; asm("cvt.rn.bf16x2.f32 %0, %1, %2;" : "=r"(r) : "f"(hi_elem), "f"(lo_elem)); return r;
}
__device__ __forceinline__ float2 bf16x2_back(uint32_t p){
    return make_float2(__uint_as_float(p << 16), __uint_as_float(p & 0xffff0000u));
}
__device__ __forceinline__ void split2(float x, float y, uint32_t& h, uint32_t& l){
    h = bf16x2_of(x, y);
    float2 hb = bf16x2_back(h);
    l = bf16x2_of(x - hb.x, y - hb.y);
}

__device__ __forceinline__ uint32_t smem_u32(const void* p){
    uint32_t a;
    asm("{ .reg .u64 t; cvta.to.shared.u64 t, %1; cvt.u32.u64 %0, t; }" : "=r"(a) : "l"(p));
    return a;
}

__device__ __forceinline__ void ldsm_x4(uint32_t* r, uint32_t addr){
    asm volatile("ldmatrix.sync.aligned.m8n8.x4.shared.b16 {%0,%1,%2,%3}, [%4];"
        : "=r"(r[0]), "=r"(r[1]), "=r"(r[2]), "=r"(r[3]) : "r"(addr));
}
__device__ __forceinline__ void mma16816(float* c, const uint32_t* a, uint32_t b0, uint32_t b1){
    asm volatile("mma.sync.aligned.m16n8k16.row.col.f32.bf16.bf16.f32 "
        "{%0,%1,%2,%3}, {%4,%5,%6,%7}, {%8,%9}, {%0,%1,%2,%3};"
        : "+f"(c[0]), "+f"(c[1]), "+f"(c[2]), "+f"(c[3])
        : "r"(a[0]), "r"(a[1]), "r"(a[2]), "r"(a[3]), "r"(b0), "r"(b1));
}

#define EL_STRIDE 72
#define EL_BUF (128*EL_STRIDE*2)          // 18432 B per buffer (128 rows x 64 bf16, stride 72)
#define EL_SMEM_BYTES (4*EL_BUF)          // 73728 B

// ---------------- init: zero counters + ei_sl output ----------------
__global__ void k_init(float* __restrict__ out_ei, const int* __restrict__ ei){
    int i = blockIdx.x*blockDim.x + threadIdx.x;
    if (i < NN) g_cnt[i] = 0;
    if (i < EN){
        int s = (i < EE) ? ei[i]     : (i-EE);
        int d = (i < EE) ? ei[EE+i]  : (i-EE);
        out_ei[i]    = (float)s;
        out_ei[EN+i] = (float)d;
    }
}

// ---------------- CSR build ----------------
__global__ void k_count(const int* __restrict__ ei){
    int i = blockIdx.x*blockDim.x + threadIdx.x;
    if (i < EE) atomicAdd(&g_cnt[ei[EE+i]], 1);
}

__global__ void k_scan(){
    __shared__ int part[1024];
    int t = threadIdx.x;
    const int chunk = (NN + 1023)/1024;
    int b = t*chunk;
    int sum = 0;
    for (int i = 0; i < chunk; i++){ int idx = b+i; if (idx < NN) sum += g_cnt[idx]; }
    part[t] = sum;
    __syncthreads();
    for (int off = 1; off < 1024; off <<= 1){
        int v = (t >= off) ? part[t-off] : 0;
        __syncthreads();
        part[t] += v;
        __syncthreads();
    }
    int run = (t == 0) ? 0 : part[t-1];
    for (int i = 0; i < chunk; i++){
        int idx = b+i;
        if (idx < NN){ g_off[idx] = run; g_cur[idx] = run; run += g_cnt[idx]; }
    }
    if (t == 1023) g_off[NN] = run;
}

__global__ void k_scatter(const int* __restrict__ ei){
    int i = blockIdx.x*blockDim.x + threadIdx.x;
    if (i >= EE) return;
    int d = ei[EE+i];
    int p = atomicAdd(&g_cur[d], 1);
    g_srow[p] = i;
    g_ssrc[p] = ei[i];
}

// ---------------- loop attr: CSR gather mean (warp per node, float2) ----------------
__global__ void k_loopattr(const float* __restrict__ ea){
    int t = blockIdx.x*blockDim.x + threadIdx.x;
    int n = t >> 5, lane = t & 31;
    if (n >= NN) return;
    int beg = g_off[n], end = g_off[n+1];
    float a0 = 0.f, a1 = 0.f;
    for (int idx = beg; idx < end; idx++){
        int row = g_srow[idx];
        float2 v = *(const float2*)&ea[(size_t)row*EDIM + lane*2];
        a0 += v.x; a1 += v.y;
    }
    float inv = 1.f / fmaxf((float)(end-beg), 1.f);
    *(float2*)&g_loop[(size_t)n*EDIM + lane*2] = make_float2(a0*inv, a1*inv);
}

// ---------------- HMMA GEMM: C = A * B^T (+bias)(+gelu), bf16-split 3-pass ----------------
// 128M x 128N tile, K-loop over BK=64 chunks. 256 threads = 8 warps, warp owns 16 rows.
template<int ABUF, int CBUF, bool BIAS, bool GELU>
__global__ __launch_bounds__(256) void hgemm(
    const float* __restrict__ Aext, const float* __restrict__ Bw,
    const float* __restrict__ bias, float* __restrict__ Cext,
    int M, int Ncol, int K)
{
    const float* A = bufsel<ABUF>(Aext);
    float* C = bufsel<CBUF>((const float*)Cext);
    extern __shared__ __align__(16) uint8_t dynsmem[];
    uint16_t* Ah = (uint16_t*)(dynsmem);
    uint16_t* Al = (uint16_t*)(dynsmem + EL_BUF);
    uint16_t* Bh = (uint16_t*)(dynsmem + 2*EL_BUF);
    uint16_t* Bl = (uint16_t*)(dynsmem + 3*EL_BUF);

    int tid = threadIdx.x;
    int w = tid >> 5, lane = tid & 31;
    int row0 = blockIdx.y * 128, col0 = blockIdx.x * 128;
    int m0 = w*16;

    float acc[16][4];
    #pragma unroll
    for (int j=0;j<16;j++){ acc[j][0]=0.f; acc[j][1]=0.f; acc[j][2]=0.f; acc[j][3]=0.f; }

    int crow = tid >> 1, chalf = tid & 1;
    int cb = chalf*32;
    int gm = row0 + crow;

    int arow_l = m0 + (lane & 15);
    int akoff  = (lane >> 4) * 8;
    uint32_t addrAh = smem_u32(Ah) + (arow_l*EL_STRIDE + akoff)*2;
    uint32_t addrAl = smem_u32(Al) + (arow_l*EL_STRIDE + akoff)*2;
    int brow_l = (lane & 7) + ((lane >> 4) << 3);
    int bkoff  = ((lane >> 3) & 1) * 8;
    uint32_t addrBh = smem_u32(Bh) + (brow_l*EL_STRIDE + bkoff)*2;
    uint32_t addrBl = smem_u32(Bl) + (brow_l*EL_STRIDE + bkoff)*2;

    for (int k0 = 0; k0 < K; k0 += 64){
        // convert chunk: thread handles row crow, 32-col half chalf
        {
            const float* arow = (gm < M) ? &A[(size_t)gm*K + k0 + cb] : nullptr;
            const float* brow = &Bw[(size_t)(col0+crow)*K + k0 + cb];
            #pragma unroll
            for (int q = 0; q < 8; q++){
                int col = cb + q*4;
                uint32_t h0, l0, h1, l1;
                if (!arow){ h0=l0=h1=l1=0u; }
                else {
                    float4 v = *(const float4*)&arow[q*4];
                    split2(v.x, v.y, h0, l0);
                    split2(v.z, v.w, h1, l1);
                }
                *(uint2*)&Ah[crow*EL_STRIDE + col] = make_uint2(h0, h1);
                *(uint2*)&Al[crow*EL_STRIDE + col] = make_uint2(l0, l1);
                {
                    float4 v = *(const float4*)&brow[q*4];
                    uint32_t bh0, bl0, bh1, bl1;
                    split2(v.x, v.y, bh0, bl0);
                    split2(v.z, v.w, bh1, bl1);
                    *(uint2*)&Bh[crow*EL_STRIDE + col] = make_uint2(bh0, bh1);
                    *(uint2*)&Bl[crow*EL_STRIDE + col] = make_uint2(bl0, bl1);
                }
            }
        }
        __syncthreads();
        #pragma unroll
        for (int kk = 0; kk < 4; kk++){
            uint32_t kofs = (kk*16)*2;
            uint32_t ah[4], al[4];
            ldsm_x4(ah, addrAh + kofs);
            ldsm_x4(al, addrAl + kofs);
            #pragma unroll
            for (int jj = 0; jj < 8; jj++){
                uint32_t bofs = (jj*16*EL_STRIDE)*2 + kofs;
                uint32_t bh[4], bl[4];
                ldsm_x4(bh, addrBh + bofs);
                ldsm_x4(bl, addrBl + bofs);
                mma16816(acc[2*jj],   ah, bh[0], bh[1]);
                mma16816(acc[2*jj+1], ah, bh[2], bh[3]);
                mma16816(acc[2*jj],   ah, bl[0], bl[1]);
                mma16816(acc[2*jj+1], ah, bl[2], bl[3]);
                mma16816(acc[2*jj],   al, bh[0], bh[1]);
                mma16816(acc[2*jj+1], al, bh[2], bh[3]);
            }
        }
        __syncthreads();
    }

    // epilogue on fragment layout: thread holds rows (m0+qid, +8), cols j*8+(lane&3)*2
    int qid = lane >> 2;
    int r0 = row0 + m0 + qid, r1 = r0 + 8;
    int cbase = (lane & 3)*2;
    #pragma unroll
    for (int j = 0; j < 16; j++){
        int c = col0 + j*8 + cbase;
        float v0 = acc[j][0], v1 = acc[j][1], v2 = acc[j][2], v3 = acc[j][3];
        if (BIAS){
            float2 bv = *(const float2*)&bias[c];
            v0 += bv.x; v1 += bv.y; v2 += bv.x; v3 += bv.y;
        }
        if (GELU){
            v0 = 0.5f*v0*(1.f + erff(v0*0.70710678118654752f));
            v1 = 0.5f*v1*(1.f + erff(v1*0.70710678118654752f));
            v2 = 0.5f*v2*(1.f + erff(v2*0.70710678118654752f));
            v3 = 0.5f*v3*(1.f + erff(v3*0.70710678118654752f));
        }
        if (r0 < M) *(float2*)&C[(size_t)r0*Ncol + c] = make_float2(v0, v1);
        if (r1 < M) *(float2*)&C[(size_t)r1*Ncol + c] = make_float2(v2, v3);
    }
}

// ---------------- fused e-projection + logits via mma.sync bf16-split ----------------
__global__ __launch_bounds__(256) void k_elogits_hmma(
    const int* __restrict__ ei, const float* __restrict__ ea,
    const float* __restrict__ We, const float* __restrict__ att,
    float* __restrict__ alpha)
{
    extern __shared__ __align__(16) uint8_t dynsmem[];
    __shared__ int s_src[128], s_dst[128];
    __shared__ float s_att[128];

    uint16_t* Ah = (uint16_t*)(dynsmem);
    uint16_t* Al = (uint16_t*)(dynsmem + EL_BUF);
    uint16_t* Bh = (uint16_t*)(dynsmem + 2*EL_BUF);
    uint16_t* Bl = (uint16_t*)(dynsmem + 3*EL_BUF);

    int tid = threadIdx.x;
    int w = tid >> 5, lane = tid & 31;
    int row0 = blockIdx.x * 128;

    if (tid < 128){
        int e = row0 + tid;
        int s, d;
        if (e < EE){ s = ei[e]; d = ei[EE+e]; }
        else if (e < EN){ s = e-EE; d = e-EE; }
        else { s = 0; d = 0; }
        s_src[tid] = s; s_dst[tid] = d;
        s_att[tid] = att[tid];
    }

    {
        int row = tid >> 1, half = tid & 1;
        int cb = half*32;
        int eg = row0 + row;
        const float* arow = nullptr;
        bool zero = false;
        if (eg < EE)      arow = &ea[(size_t)eg*EDIM + cb];
        else if (eg < EN) arow = &g_loop[(size_t)(eg-EE)*EDIM + cb];
        else              zero = true;
        const float* brow = &We[(size_t)row*EDIM + cb];
        #pragma unroll
        for (int q = 0; q < 8; q++){
            int col = cb + q*4;
            uint32_t h0, l0, h1, l1;
            if (zero){ h0=l0=h1=l1=0u; }
            else {
                float4 v = *(const float4*)&arow[q*4];
                split2(v.x, v.y, h0, l0);
                split2(v.z, v.w, h1, l1);
            }
            *(uint2*)&Ah[row*EL_STRIDE + col] = make_uint2(h0, h1);
            *(uint2*)&Al[row*EL_STRIDE + col] = make_uint2(l0, l1);
            {
                float4 v = *(const float4*)&brow[q*4];
                uint32_t bh0, bl0, bh1, bl1;
                split2(v.x, v.y, bh0, bl0);
                split2(v.z, v.w, bh1, bl1);
                *(uint2*)&Bh[row*EL_STRIDE + col] = make_uint2(bh0, bh1);
                *(uint2*)&Bl[row*EL_STRIDE + col] = make_uint2(bl0, bl1);
            }
        }
    }
    __syncthreads();

    int m0 = w*16;
    float acc[16][4];
    #pragma unroll
    for (int j=0;j<16;j++){ acc[j][0]=0.f; acc[j][1]=0.f; acc[j][2]=0.f; acc[j][3]=0.f; }

    int arow_l = m0 + (lane & 15);
    int akoff  = (lane >> 4) * 8;
    uint32_t addrAh = smem_u32(Ah) + (arow_l*EL_STRIDE + akoff)*2;
    uint32_t addrAl = smem_u32(Al) + (arow_l*EL_STRIDE + akoff)*2;
    int brow_l = (lane & 7) + ((lane >> 4) << 3);
    int bkoff  = ((lane >> 3) & 1) * 8;
    uint32_t addrBh = smem_u32(Bh) + (brow_l*EL_STRIDE + bkoff)*2;
    uint32_t addrBl = smem_u32(Bl) + (brow_l*EL_STRIDE + bkoff)*2;

    #pragma unroll
    for (int kk = 0; kk < 4; kk++){
        uint32_t kofs = (kk*16)*2;
        uint32_t ah[4], al[4];
        ldsm_x4(ah, addrAh + kofs);
        ldsm_x4(al, addrAl + kofs);
        #pragma unroll
        for (int jj = 0; jj < 8; jj++){
            uint32_t bofs = (jj*16*EL_STRIDE)*2 + kofs;
            uint32_t bh[4], bl[4];
            ldsm_x4(bh, addrBh + bofs);
            ldsm_x4(bl, addrBl + bofs);
            mma16816(acc[2*jj],   ah, bh[0], bh[1]);
            mma16816(acc[2*jj+1], ah, bh[2], bh[3]);
            mma16816(acc[2*jj],   ah, bl[0], bl[1]);
            mma16816(acc[2*jj+1], ah, bl[2], bl[3]);
            mma16816(acc[2*jj],   al, bh[0], bh[1]);
            mma16816(acc[2*jj+1], al, bh[2], bh[3]);
        }
    }

    int qid = lane >> 2;
    int r0 = m0 + qid, r1 = r0 + 8;
    int eg0 = row0 + r0, eg1 = row0 + r1;
    int sA = s_src[r0], dA = s_dst[r0];
    int sB = s_src[r1], dB = s_dst[r1];
    const float* xlA = g_xl + (size_t)sA*HC;
    const float* xrA = g_xr + (size_t)dA*HC;
    const float* xlB = g_xl + (size_t)sB*HC;
    const float* xrB = g_xr + (size_t)dB*HC;
    int cbase = (lane & 3)*2;
    float p0[4] = {0.f,0.f,0.f,0.f};
    float p1[4] = {0.f,0.f,0.f,0.f};
    #pragma unroll
    for (int j = 0; j < 16; j++){
        int c = j*8 + cbase;
        int head = j >> 2;
        float2 xl0 = *(const float2*)&xlA[c];
        float2 xr0 = *(const float2*)&xrA[c];
        float2 xl1 = *(const float2*)&xlB[c];
        float2 xr1 = *(const float2*)&xrB[c];
        float a0 = s_att[c], a1 = s_att[c+1];
        float v;
        v = acc[j][0] + xl0.x + xr0.x; v = (v>0.f)?v:0.2f*v; p0[head] += v*a0;
        v = acc[j][1] + xl0.y + xr0.y; v = (v>0.f)?v:0.2f*v; p0[head] += v*a1;
        v = acc[j][2] + xl1.x + xr1.x; v = (v>0.f)?v:0.2f*v; p1[head] += v*a0;
        v = acc[j][3] + xl1.y + xr1.y; v = (v>0.f)?v:0.2f*v; p1[head] += v*a1;
    }
    #pragma unroll
    for (int o = 1; o <= 2; o <<= 1){
        #pragma unroll
        for (int hh = 0; hh < 4; hh++){
            p0[hh] += __shfl_xor_sync(0xffffffffu, p0[hh], o);
            p1[hh] += __shfl_xor_sync(0xffffffffu, p1[hh], o);
        }
    }
    if ((lane & 3) == 0){
        if (eg0 < EN) *(float4*)&alpha[(size_t)eg0*4] = make_float4(p0[0], p0[1], p0[2], p0[3]);
        if (eg1 < EN) *(float4*)&alpha[(size_t)eg1*4] = make_float4(p1[0], p1[1], p1[2], p1[3]);
    }
}

// ---------------- online segment softmax + aggregate + residual + LN1 ----------------
__device__ __forceinline__ void online_upd(float l, float& m, float& s){
    if (l > m){ s = s*__expf(m-l) + 1.f; m = l; }
    else s += __expf(l-m);
}
__device__ __forceinline__ void online_merge(float om, float os, float& m, float& s){
    float nm = fmaxf(m, om);
    s = s*__expf(m-nm) + os*__expf(om-nm);
    m = nm;
}

__global__ void k_smagg(const float* __restrict__ x, const float* __restrict__ gbias,
                        const float* __restrict__ g1, const float* __restrict__ b1,
                        float* __restrict__ alpha)
{
    int t = blockIdx.x*blockDim.x + threadIdx.x;
    int n = t >> 5, lane = t & 31;
    if (n >= NN) return;
    int beg = g_off[n], end = g_off[n+1];
    float4* a4 = (float4*)alpha;

    float4 lsl = a4[EE+n];
    const float NEGBIG = -1e30f;
    float m0=NEGBIG,m1=NEGBIG,m2=NEGBIG,m3=NEGBIG;
    float s0=0.f,s1=0.f,s2=0.f,s3=0.f;
    for (int idx = beg + lane; idx < end; idx += 32){
        float4 l = a4[g_srow[idx]];
        online_upd(l.x, m0, s0); online_upd(l.y, m1, s1);
        online_upd(l.z, m2, s2); online_upd(l.w, m3, s3);
    }
    #pragma unroll
    for (int o = 16; o; o >>= 1){
        float om, os;
        om = __shfl_xor_sync(0xffffffffu, m0, o); os = __shfl_xor_sync(0xffffffffu, s0, o); online_merge(om, os, m0, s0);
        om = __shfl_xor_sync(0xffffffffu, m1, o); os = __shfl_xor_sync(0xffffffffu, s1, o); online_merge(om, os, m1, s1);
        om = __shfl_xor_sync(0xffffffffu, m2, o); os = __shfl_xor_sync(0xffffffffu, s2, o); online_merge(om, os, m2, s2);
        om = __shfl_xor_sync(0xffffffffu, m3, o); os = __shfl_xor_sync(0xffffffffu, s3, o); online_merge(om, os, m3, s3);
    }
    online_upd(lsl.x, m0, s0); online_upd(lsl.y, m1, s1);
    online_upd(lsl.z, m2, s2); online_upd(lsl.w, m3, s3);

    float i0 = 1.f/s0, i1 = 1.f/s1, i2 = 1.f/s2, i3 = 1.f/s3;
    float asl0 = __expf(lsl.x - m0)*i0, asl1 = __expf(lsl.y - m1)*i1;
    float asl2 = __expf(lsl.z - m2)*i2, asl3 = __expf(lsl.w - m3)*i3;
    if (lane == 0) a4[EE+n] = make_float4(asl0, asl1, asl2, asl3);
    for (int idx = beg + lane; idx < end; idx += 32){
        int row = g_srow[idx];
        float4 l = a4[row];
        a4[row] = make_float4(__expf(l.x - m0)*i0, __expf(l.y - m1)*i1,
                              __expf(l.z - m2)*i2, __expf(l.w - m3)*i3);
    }
    __syncwarp();

    int cbase = lane*4;
    int h = lane >> 3;
    float4 accv = make_float4(0.f,0.f,0.f,0.f);
    for (int idx = beg; idx < end; idx++){
        int row = g_srow[idx], src = g_ssrc[idx];
        float4 a = a4[row];
        float ah = (h==0) ? a.x : (h==1) ? a.y : (h==2) ? a.z : a.w;
        float4 xv = *(const float4*)&g_xl[(size_t)src*HC + cbase];
        accv.x += ah*xv.x; accv.y += ah*xv.y; accv.z += ah*xv.z; accv.w += ah*xv.w;
    }
    {
        float ah = (h==0) ? asl0 : (h==1) ? asl1 : (h==2) ? asl2 : asl3;
        float4 xv = *(const float4*)&g_xl[(size_t)n*HC + cbase];
        accv.x += ah*xv.x; accv.y += ah*xv.y; accv.z += ah*xv.z; accv.w += ah*xv.w;
    }

    float4 xres = *(const float4*)&x[(size_t)n*DD + cbase];
    float4 gb4  = *(const float4*)&gbias[cbase];
    float v0 = accv.x + xres.x + gb4.x;
    float v1 = accv.y + xres.y + gb4.y;
    float v2 = accv.z + xres.z + gb4.z;
    float v3 = accv.w + xres.w + gb4.w;
    float s = v0+v1+v2+v3;
    #pragma unroll
    for (int o = 16; o; o >>= 1) s += __shfl_xor_sync(0xffffffffu, s, o);
    float mu = s * (1.f/128.f);
    float q = (v0-mu)*(v0-mu) + (v1-mu)*(v1-mu) + (v2-mu)*(v2-mu) + (v3-mu)*(v3-mu);
    #pragma unroll
    for (int o = 16; o; o >>= 1) q += __shfl_xor_sync(0xffffffffu, q, o);
    float rstd = rsqrtf(q*(1.f/128.f) + 1e-5f);
    float4 g14 = *(const float4*)&g1[cbase];
    float4 b14 = *(const float4*)&b1[cbase];
    *(float4*)&g_h[(size_t)n*DD + cbase] = make_float4(
        (v0-mu)*rstd*g14.x + b14.x, (v1-mu)*rstd*g14.y + b14.y,
        (v2-mu)*rstd*g14.z + b14.z, (v3-mu)*rstd*g14.w + b14.w);
}

// ---------------- residual + LayerNorm 2 (warp per node, float4) ----------------
__global__ void k_ln2(const float* __restrict__ gam, const float* __restrict__ bet,
                      float* __restrict__ O){
    int t = blockIdx.x*blockDim.x + threadIdx.x;
    int n = t >> 5, lane = t & 31;
    if (n >= NN) return;
    int cbase = lane*4;
    float4 hv = *(const float4*)&g_h[(size_t)n*DD + cbase];
    float4 mv = *(const float4*)&g_mlp[(size_t)n*DD + cbase];
    float v0 = hv.x+mv.x, v1 = hv.y+mv.y, v2 = hv.z+mv.z, v3 = hv.w+mv.w;
    float s = v0+v1+v2+v3;
    #pragma unroll
    for (int o=16;o;o>>=1) s += __shfl_xor_sync(0xffffffffu, s, o);
    float mu = s * (1.f/128.f);
    float q = (v0-mu)*(v0-mu) + (v1-mu)*(v1-mu) + (v2-mu)*(v2-mu) + (v3-mu)*(v3-mu);
    #pragma unroll
    for (int o=16;o;o>>=1) q += __shfl_xor_sync(0xffffffffu, q, o);
    float rstd = rsqrtf(q*(1.f/128.f) + 1e-5f);
    float4 g4 = *(const float4*)&gam[cbase];
    float4 b4 = *(const float4*)&bet[cbase];
    *(float4*)&O[(size_t)n*DD + cbase] = make_float4(
        (v0-mu)*rstd*g4.x + b4.x, (v1-mu)*rstd*g4.y + b4.y,
        (v2-mu)*rstd*g4.z + b4.z, (v3-mu)*rstd*g4.w + b4.w);
}

// ---------------- launch ----------------
extern "C" void kernel_launch(void* const* d_in, const int* in_sizes, int n_in,
                              void* d_out, int out_size) {
    const float* x   = (const float*)d_in[0];
    const int*   ei  = (const int*)  d_in[1];
    const float* ea  = (const float*)d_in[2];
    const float* Wl  = (const float*)d_in[3];
    const float* bl  = (const float*)d_in[4];
    const float* Wr  = (const float*)d_in[5];
    const float* br  = (const float*)d_in[6];
    const float* We  = (const float*)d_in[7];
    const float* att = (const float*)d_in[8];
    const float* gb  = (const float*)d_in[9];
    const float* g1  = (const float*)d_in[10];
    const float* b1  = (const float*)d_in[11];
    const float* g2  = (const float*)d_in[12];
    const float* b2  = (const float*)d_in[13];
    const float* W1  = (const float*)d_in[14];
    const float* W2  = (const float*)d_in[15];

    float* out    = (float*)d_out;
    float* out_ei = out + (size_t)NN*DD;
    float* alpha  = out + (size_t)NN*DD + 2*(size_t)EN;

    cudaFuncSetAttribute(k_elogits_hmma, cudaFuncAttributeMaxDynamicSharedMemorySize, EL_SMEM_BYTES);
    cudaFuncSetAttribute(hgemm<0,1,true,false>,  cudaFuncAttributeMaxDynamicSharedMemorySize, EL_SMEM_BYTES);
    cudaFuncSetAttribute(hgemm<0,2,true,false>,  cudaFuncAttributeMaxDynamicSharedMemorySize, EL_SMEM_BYTES);
    cudaFuncSetAttribute(hgemm<6,7,false,true>,  cudaFuncAttributeMaxDynamicSharedMemorySize, EL_SMEM_BYTES);
    cudaFuncSetAttribute(hgemm<7,8,false,false>, cudaFuncAttributeMaxDynamicSharedMemorySize, EL_SMEM_BYTES);

    const int T = 256;
    k_init<<<(EN + T-1)/T, T>>>(out_ei, ei);
    k_count<<<(EE + T-1)/T, T>>>(ei);
    k_scan<<<1, 1024>>>();
    k_scatter<<<(EE + T-1)/T, T>>>(ei);
    k_loopattr<<<(NN*32 + T-1)/T, T>>>(ea);

    int rowsN = (NN + 127)/128;
    hgemm<0,1,true,false><<<dim3(1, rowsN), 256, EL_SMEM_BYTES>>>(x, Wl, bl, nullptr, NN, 128, 128);
    hgemm<0,2,true,false><<<dim3(1, rowsN), 256, EL_SMEM_BYTES>>>(x, Wr, br, nullptr, NN, 128, 128);

    k_elogits_hmma<<<(EN + 127)/128, 256, EL_SMEM_BYTES>>>(ei, ea, We, att, alpha);
    k_smagg<<<(NN*32 + T-1)/T, T>>>(x, gb, g1, b1, alpha);

    hgemm<6,7,false,true><<<dim3(2, rowsN), 256, EL_SMEM_BYTES>>>(nullptr, W1, nullptr, nullptr, NN, 256, 128);
    hgemm<7,8,false,false><<<dim3(1, rowsN), 256, EL_SMEM_BYTES>>>(nullptr, W2, nullptr, nullptr, NN, 128, 256);
    k_ln2<<<(NN*32 + T-1)/T, T>>>(g2, b2, out);
}